// round 1
// baseline (speedup 1.0000x reference)
#include <cuda_runtime.h>
#include <math.h>

// ---------------------------------------------------------------------------
// Problem constants
// ---------------------------------------------------------------------------
#define PB 2
#define PS 2048
#define PD 2048
#define PH 16
#define PHD 128
#define PM (PB * PS)          // 4096 rows

// ---------------------------------------------------------------------------
// Scratch (device globals; no allocation allowed)
// ---------------------------------------------------------------------------
__device__ float g_Q[(size_t)PM * PD];
__device__ float g_K[(size_t)PM * PD];
__device__ float g_V[(size_t)PM * PD];
__device__ float g_AO[(size_t)PM * PD];
__device__ float g_cos[PS * (PHD / 2)];
__device__ float g_sin[PS * (PHD / 2)];

// ---------------------------------------------------------------------------
// SGEMM: C[M,N] = A[M,K] @ W[N,K]^T   (both K-contiguous row-major)
// 128x128 block tile, BK=16, 256 threads, 8x8 per-thread microtile.
// ---------------------------------------------------------------------------
#define GBM 128
#define GBN 128
#define GBK 16

__global__ __launch_bounds__(256, 2)
void sgemm_abt(const float* __restrict__ A, const float* __restrict__ W,
               float* __restrict__ C, int Mm, int Nn, int Kk)
{
    __shared__ float As[GBK][GBM];
    __shared__ float Bs[GBK][GBN];

    const int tid  = threadIdx.x;
    const int bm   = blockIdx.y * GBM;
    const int bn   = blockIdx.x * GBN;
    const int tx   = tid & 15;
    const int ty   = tid >> 4;
    const int row0 = ty * 8;
    const int col0 = tx * 8;
    const int lrow = tid >> 2;          // 0..63
    const int lcol = (tid & 3) << 2;    // 0,4,8,12

    float acc[8][8];
#pragma unroll
    for (int i = 0; i < 8; ++i)
#pragma unroll
        for (int j = 0; j < 8; ++j) acc[i][j] = 0.0f;

    const float* Ab = A + (size_t)bm * Kk;
    const float* Wb = W + (size_t)bn * Kk;

    for (int k0 = 0; k0 < Kk; k0 += GBK) {
#pragma unroll
        for (int r = 0; r < 2; ++r) {
            const int rr = lrow + r * 64;
            float4 va = *(const float4*)(Ab + (size_t)rr * Kk + k0 + lcol);
            As[lcol + 0][rr] = va.x;
            As[lcol + 1][rr] = va.y;
            As[lcol + 2][rr] = va.z;
            As[lcol + 3][rr] = va.w;
            float4 vb = *(const float4*)(Wb + (size_t)rr * Kk + k0 + lcol);
            Bs[lcol + 0][rr] = vb.x;
            Bs[lcol + 1][rr] = vb.y;
            Bs[lcol + 2][rr] = vb.z;
            Bs[lcol + 3][rr] = vb.w;
        }
        __syncthreads();

#pragma unroll
        for (int k = 0; k < GBK; ++k) {
            float a[8], b[8];
            *(float4*)&a[0] = *(const float4*)&As[k][row0];
            *(float4*)&a[4] = *(const float4*)&As[k][row0 + 4];
            *(float4*)&b[0] = *(const float4*)&Bs[k][col0];
            *(float4*)&b[4] = *(const float4*)&Bs[k][col0 + 4];
#pragma unroll
            for (int i = 0; i < 8; ++i)
#pragma unroll
                for (int j = 0; j < 8; ++j)
                    acc[i][j] = fmaf(a[i], b[j], acc[i][j]);
        }
        __syncthreads();
    }

#pragma unroll
    for (int i = 0; i < 8; ++i) {
        float* cp = C + (size_t)(bm + row0 + i) * Nn + bn + col0;
        float4 v0 = make_float4(acc[i][0], acc[i][1], acc[i][2], acc[i][3]);
        float4 v1 = make_float4(acc[i][4], acc[i][5], acc[i][6], acc[i][7]);
        *(float4*)cp       = v0;
        *(float4*)(cp + 4) = v1;
    }
}

// ---------------------------------------------------------------------------
// RoPE tables: angle computed on the fp32-rounded chain (matches reference),
// trig evaluated in double to avoid fast-math sinf catastrophe at |x|~2000.
// ---------------------------------------------------------------------------
__global__ void rope_tables(float* __restrict__ ct, float* __restrict__ st)
{
    int idx = blockIdx.x * blockDim.x + threadIdx.x;
    if (idx >= PS * (PHD / 2)) return;
    int s = idx >> 6;       // / 64
    int j = idx & 63;
    float invf = (float)pow(10000.0, -(double)j / 64.0);  // fp32-rounded inv_freq
    float ang  = (float)s * invf;                          // fp32-rounded angle
    double a   = (double)ang;
    ct[idx] = (float)cos(a);
    st[idx] = (float)sin(a);
}

// ---------------------------------------------------------------------------
// RoPE apply (in-place on Q and K, layout [B,S,H*HD])
// one block per (b,s) row; stage row in smem so halves pair safely.
// ---------------------------------------------------------------------------
__global__ __launch_bounds__(256)
void rope_apply(float* __restrict__ Q, float* __restrict__ Kv,
                const float* __restrict__ ct, const float* __restrict__ st)
{
    const int row = blockIdx.x;           // b*S + s
    const int s   = row & (PS - 1);
    const int tid = threadIdx.x;
    __shared__ float buf[PD];

#pragma unroll
    for (int pass = 0; pass < 2; ++pass) {
        float* ptr = (pass == 0 ? Q : Kv) + (size_t)row * PD;
        for (int i = tid; i < PD; i += 256) buf[i] = ptr[i];
        __syncthreads();
        for (int i = tid; i < PD; i += 256) {
            int d = i & (PHD - 1);
            int j = d & 63;
            float c  = ct[s * 64 + j];
            float sn = st[s * 64 + j];
            float x  = buf[i];
            float xr = (d < 64) ? -buf[i + 64] : buf[i - 64];
            ptr[i] = fmaf(x, c, xr * sn);
        }
        __syncthreads();
    }
}

// ---------------------------------------------------------------------------
// Causal flash attention, fp32.
// Tile: 64 queries x 64 keys, HD=128. 256 threads = 16x16.
// Thread (tx,ty): score microtile rows ty*4+ii, cols jj*16+tx (conflict-free).
// O accumulators: rows ty*4+ii, cols jj*16+tx (jj 0..7).
// Q/K/V in [B,S,H*HD]; O written to [B,S,H*HD].
// ---------------------------------------------------------------------------
#define AQP (PHD + 1)   // 129 pitch for Q/K/V smem tiles
#define APP 65          // pitch for P tile
#define ATTN_SMEM ((3 * 64 * AQP + 64 * APP) * (int)sizeof(float))  // 115712 B

__global__ __launch_bounds__(256)
void attn_fwd(const float* __restrict__ Q, const float* __restrict__ K,
              const float* __restrict__ V, float* __restrict__ O)
{
    extern __shared__ float smattn[];
    float* Qs = smattn;               // 64 * 129
    float* Ks = Qs + 64 * AQP;        // 64 * 129
    float* Vs = Ks + 64 * AQP;        // 64 * 129
    float* Ps = Vs + 64 * AQP;        // 64 * 65

    const int tid = threadIdx.x;
    const int tx  = tid & 15;
    const int ty  = tid >> 4;
    const int qt  = blockIdx.x;       // query tile (0..31)
    const int bh  = blockIdx.y;       // 0..31
    const int b   = bh >> 4;
    const int h   = bh & 15;
    const int qbase = qt * 64;

    const float scale = 0.08838834764831845f;   // 1/sqrt(128)

    const float* qg = Q + ((size_t)b * PS) * PD + (size_t)h * PHD;
    const float* kg = K + ((size_t)b * PS) * PD + (size_t)h * PHD;
    const float* vg = V + ((size_t)b * PS) * PD + (size_t)h * PHD;

    // Load Q tile (64 rows x 128 cols), coalesced: one row = 32 float4.
    for (int i = tid; i < 64 * 32; i += 256) {
        int r = i >> 5;
        int c = (i & 31) << 2;
        float4 v = *(const float4*)(qg + (size_t)(qbase + r) * PD + c);
        float* dst = Qs + r * AQP + c;
        dst[0] = v.x; dst[1] = v.y; dst[2] = v.z; dst[3] = v.w;
    }

    float m[4], l[4], o[4][8];
#pragma unroll
    for (int ii = 0; ii < 4; ++ii) {
        m[ii] = -INFINITY;
        l[ii] = 0.0f;
#pragma unroll
        for (int jj = 0; jj < 8; ++jj) o[ii][jj] = 0.0f;
    }

    for (int kt = 0; kt <= qt; ++kt) {
        const int kbase = kt * 64;
        __syncthreads();   // protect Ks/Vs against previous iteration's readers
        for (int i = tid; i < 64 * 32; i += 256) {
            int r = i >> 5;
            int c = (i & 31) << 2;
            float4 vk = *(const float4*)(kg + (size_t)(kbase + r) * PD + c);
            float* dk = Ks + r * AQP + c;
            dk[0] = vk.x; dk[1] = vk.y; dk[2] = vk.z; dk[3] = vk.w;
            float4 vv = *(const float4*)(vg + (size_t)(kbase + r) * PD + c);
            float* dv = Vs + r * AQP + c;
            dv[0] = vv.x; dv[1] = vv.y; dv[2] = vv.z; dv[3] = vv.w;
        }
        __syncthreads();

        // S = Q @ K^T  (4x4 microtile per thread)
        float sc[4][4];
#pragma unroll
        for (int ii = 0; ii < 4; ++ii)
#pragma unroll
            for (int jj = 0; jj < 4; ++jj) sc[ii][jj] = 0.0f;

        const float* q0 = Qs + (ty * 4) * AQP;
        const float* k0 = Ks + tx * AQP;
#pragma unroll 4
        for (int d = 0; d < PHD; ++d) {
            float av[4], bv[4];
            av[0] = q0[d];
            av[1] = q0[AQP + d];
            av[2] = q0[2 * AQP + d];
            av[3] = q0[3 * AQP + d];
            bv[0] = k0[d];
            bv[1] = k0[16 * AQP + d];
            bv[2] = k0[32 * AQP + d];
            bv[3] = k0[48 * AQP + d];
#pragma unroll
            for (int ii = 0; ii < 4; ++ii)
#pragma unroll
                for (int jj = 0; jj < 4; ++jj)
                    sc[ii][jj] = fmaf(av[ii], bv[jj], sc[ii][jj]);
        }

        // scale + causal mask (diagonal tile only)
        if (kt == qt) {
#pragma unroll
            for (int ii = 0; ii < 4; ++ii) {
                const int qi = ty * 4 + ii;
#pragma unroll
                for (int jj = 0; jj < 4; ++jj) {
                    const int kj = jj * 16 + tx;
                    sc[ii][jj] = (kj <= qi) ? sc[ii][jj] * scale : -INFINITY;
                }
            }
        } else {
#pragma unroll
            for (int ii = 0; ii < 4; ++ii)
#pragma unroll
                for (int jj = 0; jj < 4; ++jj) sc[ii][jj] *= scale;
        }

        // online softmax (row stats reduced across the 16 tx lanes)
#pragma unroll
        for (int ii = 0; ii < 4; ++ii) {
            float rm = fmaxf(fmaxf(sc[ii][0], sc[ii][1]),
                             fmaxf(sc[ii][2], sc[ii][3]));
#pragma unroll
            for (int off = 8; off >= 1; off >>= 1)
                rm = fmaxf(rm, __shfl_xor_sync(0xffffffffu, rm, off));
            float mn = fmaxf(m[ii], rm);
            float p0 = __expf(sc[ii][0] - mn);
            float p1 = __expf(sc[ii][1] - mn);
            float p2 = __expf(sc[ii][2] - mn);
            float p3 = __expf(sc[ii][3] - mn);
            float rs = (p0 + p1) + (p2 + p3);
#pragma unroll
            for (int off = 8; off >= 1; off >>= 1)
                rs += __shfl_xor_sync(0xffffffffu, rs, off);
            float corr = __expf(m[ii] - mn);
            m[ii] = mn;
            l[ii] = l[ii] * corr + rs;
#pragma unroll
            for (int jj = 0; jj < 8; ++jj) o[ii][jj] *= corr;
            float* prow = Ps + (ty * 4 + ii) * APP;
            prow[tx]      = p0;
            prow[16 + tx] = p1;
            prow[32 + tx] = p2;
            prow[48 + tx] = p3;
        }
        __syncthreads();

        // O += P @ V
#pragma unroll 2
        for (int j = 0; j < 64; ++j) {
            float pv[4];
#pragma unroll
            for (int ii = 0; ii < 4; ++ii)
                pv[ii] = Ps[(ty * 4 + ii) * APP + j];
            const float* vj = Vs + j * AQP + tx;
#pragma unroll
            for (int jj = 0; jj < 8; ++jj) {
                float vvv = vj[jj * 16];
#pragma unroll
                for (int ii = 0; ii < 4; ++ii)
                    o[ii][jj] = fmaf(pv[ii], vvv, o[ii][jj]);
            }
        }
    }

    // epilogue: normalize and store to [B,S,H*HD]
#pragma unroll
    for (int ii = 0; ii < 4; ++ii) {
        float inv = 1.0f / l[ii];
        float* orow = O + ((size_t)b * PS + qbase + ty * 4 + ii) * PD
                        + (size_t)h * PHD + tx;
#pragma unroll
        for (int jj = 0; jj < 8; ++jj)
            orow[jj * 16] = o[ii][jj] * inv;
    }
}

// ---------------------------------------------------------------------------
// kernel_launch
// ---------------------------------------------------------------------------
extern "C" void kernel_launch(void* const* d_in, const int* in_sizes, int n_in,
                              void* d_out, int out_size)
{
    const float* x  = (const float*)d_in[0];
    const float* Wq = (const float*)d_in[1];
    const float* Wk = (const float*)d_in[2];
    const float* Wv = (const float*)d_in[3];
    const float* Wo = (const float*)d_in[4];
    float* out = (float*)d_out;

    float *Qp, *Kp, *Vp, *AOp, *cp, *sp;
    cudaGetSymbolAddress((void**)&Qp,  g_Q);
    cudaGetSymbolAddress((void**)&Kp,  g_K);
    cudaGetSymbolAddress((void**)&Vp,  g_V);
    cudaGetSymbolAddress((void**)&AOp, g_AO);
    cudaGetSymbolAddress((void**)&cp,  g_cos);
    cudaGetSymbolAddress((void**)&sp,  g_sin);

    cudaFuncSetAttribute(attn_fwd,
                         cudaFuncAttributeMaxDynamicSharedMemorySize,
                         ATTN_SMEM);

    dim3 gemm_grid(PD / GBN, PM / GBM);   // (16, 32)

    // Q/K/V projections
    sgemm_abt<<<gemm_grid, 256>>>(x, Wq, Qp, PM, PD, PD);
    sgemm_abt<<<gemm_grid, 256>>>(x, Wk, Kp, PM, PD, PD);
    sgemm_abt<<<gemm_grid, 256>>>(x, Wv, Vp, PM, PD, PD);

    // RoPE
    rope_tables<<<(PS * 64 + 255) / 256, 256>>>(cp, sp);
    rope_apply<<<PM, 256>>>(Qp, Kp, cp, sp);

    // causal flash attention
    attn_fwd<<<dim3(PS / 64, PB * PH), 256, ATTN_SMEM>>>(Qp, Kp, Vp, AOp);

    // output projection
    sgemm_abt<<<gemm_grid, 256>>>(AOp, Wo, out, PM, PD, PD);
}

// round 3
// speedup vs baseline: 1.7859x; 1.7859x over previous
#include <cuda_runtime.h>
#include <cuda_bf16.h>
#include <math.h>
#include <stdint.h>

// ---------------------------------------------------------------------------
// Problem constants
// ---------------------------------------------------------------------------
#define PB 2
#define PS 2048
#define PD 2048
#define PH 16
#define PHD 128
#define PM (PB * PS)          // 4096 rows
#define K3 (3 * PD)           // 6144: split-K for bf16x3

// ---------------------------------------------------------------------------
// Scratch (device globals; no allocation allowed)
// ---------------------------------------------------------------------------
__device__ float g_Q[(size_t)PM * PD];
__device__ float g_K[(size_t)PM * PD];
__device__ float g_V[(size_t)PM * PD];
__device__ float g_AO[(size_t)PM * PD];
__device__ float g_cos[PS * (PHD / 2)];
__device__ float g_sin[PS * (PHD / 2)];
__device__ __nv_bfloat16 g_Ax[(size_t)PM * K3];     // activations, split
__device__ __nv_bfloat16 g_Bq[(size_t)PD * K3];
__device__ __nv_bfloat16 g_Bk[(size_t)PD * K3];
__device__ __nv_bfloat16 g_Bv[(size_t)PD * K3];
__device__ __nv_bfloat16 g_Bo[(size_t)PD * K3];

// ---------------------------------------------------------------------------
// PTX helpers (sm_80-compatible: cp.async + ldmatrix + mma.sync)
// ---------------------------------------------------------------------------
__device__ __forceinline__ uint32_t smem_u32(const void* p) {
    uint32_t a;
    asm("{ .reg .u64 t; cvta.to.shared.u64 t, %1; cvt.u32.u64 %0, t; }"
        : "=r"(a) : "l"(p));
    return a;
}

#define CP_ASYNC16(smem, gptr) \
    asm volatile("cp.async.cg.shared.global [%0], [%1], 16;" \
                 :: "r"(smem), "l"(gptr) : "memory")
#define CP_COMMIT() asm volatile("cp.async.commit_group;" ::: "memory")
#define CP_WAIT2()  asm volatile("cp.async.wait_group 2;" ::: "memory")
#define CP_WAIT0()  asm volatile("cp.async.wait_group 0;" ::: "memory")

#define LDSM_X4(r0, r1, r2, r3, addr) \
    asm volatile("ldmatrix.sync.aligned.m8n8.x4.shared.b16 {%0,%1,%2,%3}, [%4];" \
                 : "=r"(r0), "=r"(r1), "=r"(r2), "=r"(r3) : "r"(addr))
#define LDSM_X2(r0, r1, addr) \
    asm volatile("ldmatrix.sync.aligned.m8n8.x2.shared.b16 {%0,%1}, [%2];" \
                 : "=r"(r0), "=r"(r1) : "r"(addr))

#define MMA_16816(c0, c1, c2, c3, a0, a1, a2, a3, b0, b1) \
    asm volatile("mma.sync.aligned.m16n8k16.row.col.f32.bf16.bf16.f32 " \
                 "{%0,%1,%2,%3}, {%4,%5,%6,%7}, {%8,%9}, {%0,%1,%2,%3};" \
                 : "+f"(c0), "+f"(c1), "+f"(c2), "+f"(c3) \
                 : "r"(a0), "r"(a1), "r"(a2), "r"(a3), "r"(b0), "r"(b1))

// ---------------------------------------------------------------------------
// Split fp32 -> 3-segment bf16: order=0 (activations): [hi | hi | lo]
//                               order=1 (weights):     [hi | lo | hi]
// ---------------------------------------------------------------------------
__global__ void split3(const float* __restrict__ X, __nv_bfloat16* __restrict__ Y,
                       int order, int npairs)
{
    int i = blockIdx.x * blockDim.x + threadIdx.x;
    if (i >= npairs) return;
    int r = i >> 10;            // 1024 pairs per 2048-col row
    int c = (i & 1023) << 1;
    float2 v = *(const float2*)(X + (size_t)r * PD + c);
    __nv_bfloat16 h0 = __float2bfloat16(v.x);
    __nv_bfloat16 h1 = __float2bfloat16(v.y);
    __nv_bfloat16 l0 = __float2bfloat16(v.x - __bfloat162float(h0));
    __nv_bfloat16 l1 = __float2bfloat16(v.y - __bfloat162float(h1));
    __nv_bfloat162 hh = __halves2bfloat162(h0, h1);
    __nv_bfloat162 ll = __halves2bfloat162(l0, l1);
    __nv_bfloat162* base = (__nv_bfloat162*)(Y + (size_t)r * K3 + c);
    base[0]    = hh;
    base[1024] = order ? ll : hh;
    base[2048] = order ? hh : ll;
}

// ---------------------------------------------------------------------------
// HMMA bf16 GEMM: C[4096,2048] = A3[4096,6144] @ B3[2048,6144]^T (fp32 acc)
// 128x128 CTA tile, BK=32, 4-stage cp.async pipeline, 8 warps x (64x32).
// smem stage: A 128x32 bf16 (8KB) + B 128x32 (8KB), XOR-swizzled 16B chunks.
// ---------------------------------------------------------------------------
#define HG_BM 128
#define HG_BN 128
#define HG_BK 32
#define HG_STG 4
#define HG_STAGE_BYTES 16384
#define HG_SMEM (HG_STG * HG_STAGE_BYTES)   // 65536
#define HG_KT (K3 / HG_BK)                   // 192

// swizzled byte offset within an 8KB tile: row r (0..127) of 32 bf16, chunk ch (0..3 x 16B)
__device__ __forceinline__ uint32_t hg_sw(int r, int ch) {
    return (uint32_t)(r * 64 + ((ch ^ ((r >> 1) & 3)) << 4));
}

__global__ __launch_bounds__(256, 2)
void gemm_hmma(const __nv_bfloat16* __restrict__ A3,
               const __nv_bfloat16* __restrict__ B3,
               float* __restrict__ C)
{
    extern __shared__ __align__(1024) char smem[];
    const uint32_t sbase = smem_u32(smem);

    const int tid  = threadIdx.x;
    const int lane = tid & 31;
    const int wid  = tid >> 5;
    const int wm   = wid & 1;          // warp m (0..1), tile 64 rows
    const int wn   = wid >> 1;         // warp n (0..3), tile 32 cols
    const int bm   = blockIdx.y * HG_BM;
    const int bn   = blockIdx.x * HG_BN;

    const __nv_bfloat16* Ag = A3 + (size_t)bm * K3;
    const __nv_bfloat16* Bg = B3 + (size_t)bn * K3;

    // ---- loader thread mapping: 2 A chunks + 2 B chunks per thread per stage
    int lr[2], lc[2];
    uint32_t lsw[2];
    const __nv_bfloat16* gA[2];
    const __nv_bfloat16* gB[2];
#pragma unroll
    for (int p = 0; p < 2; ++p) {
        int idx = tid + p * 256;       // 0..511
        lr[p] = idx >> 2;              // row 0..127
        lc[p] = idx & 3;               // chunk
        lsw[p] = hg_sw(lr[p], lc[p]);
        gA[p] = Ag + (size_t)lr[p] * K3 + lc[p] * 8;
        gB[p] = Bg + (size_t)lr[p] * K3 + lc[p] * 8;
    }

    // ---- ldmatrix address components (constant swizzle per lane)
    // A frags: mi 0..3, rows wm*64 + mi*16 + (lane&15), chunk (2h + lane>>4)
    uint32_t a_row_off[4];
    int a_swz[4];
#pragma unroll
    for (int mi = 0; mi < 4; ++mi) {
        int r = wm * 64 + mi * 16 + (lane & 15);
        a_row_off[mi] = (uint32_t)(r * 64);
        a_swz[mi] = (r >> 1) & 3;
    }
    const int a_cpart = lane >> 4;      // 0 or 1
    // B frags: nj 0..3, rows wn*32 + nj*8 + (lane&7), chunk (2h + (lane>>3)&1)
    uint32_t b_row_off[4];
    int b_swz[4];
#pragma unroll
    for (int nj = 0; nj < 4; ++nj) {
        int r = wn * 32 + nj * 8 + (lane & 7);
        b_row_off[nj] = (uint32_t)(r * 64);
        b_swz[nj] = (r >> 1) & 3;
    }
    const int b_cpart = (lane >> 3) & 1;

    float acc[4][4][4];
#pragma unroll
    for (int mi = 0; mi < 4; ++mi)
#pragma unroll
        for (int nj = 0; nj < 4; ++nj)
#pragma unroll
            for (int e = 0; e < 4; ++e) acc[mi][nj][e] = 0.0f;

    // ---- prologue: issue stages 0..2
#pragma unroll
    for (int s = 0; s < HG_STG - 1; ++s) {
        uint32_t sA = sbase + s * HG_STAGE_BYTES;
        uint32_t sB = sA + 8192;
        int k0 = s * HG_BK;
#pragma unroll
        for (int p = 0; p < 2; ++p) {
            CP_ASYNC16(sA + lsw[p], gA[p] + k0);
            CP_ASYNC16(sB + lsw[p], gB[p] + k0);
        }
        CP_COMMIT();
    }

    for (int kt = 0; kt < HG_KT; ++kt) {
        CP_WAIT2();
        __syncthreads();

        // issue stage kt+3
        int nk = kt + HG_STG - 1;
        if (nk < HG_KT) {
            uint32_t sA = sbase + (nk & 3) * HG_STAGE_BYTES;
            uint32_t sB = sA + 8192;
            int k0 = nk * HG_BK;
#pragma unroll
            for (int p = 0; p < 2; ++p) {
                CP_ASYNC16(sA + lsw[p], gA[p] + k0);
                CP_ASYNC16(sB + lsw[p], gB[p] + k0);
            }
        }
        CP_COMMIT();

        // compute stage kt
        uint32_t sA = sbase + (kt & 3) * HG_STAGE_BYTES;
        uint32_t sB = sA + 8192;
#pragma unroll
        for (int h = 0; h < 2; ++h) {
            uint32_t a0[4], a1[4], a2[4], a3[4];
#pragma unroll
            for (int mi = 0; mi < 4; ++mi) {
                uint32_t addr = sA + a_row_off[mi]
                              + (uint32_t)(((2 * h + a_cpart) ^ a_swz[mi]) << 4);
                LDSM_X4(a0[mi], a1[mi], a2[mi], a3[mi], addr);
            }
            uint32_t b0[4], b1[4];
#pragma unroll
            for (int nj = 0; nj < 4; ++nj) {
                uint32_t addr = sB + b_row_off[nj]
                              + (uint32_t)(((2 * h + b_cpart) ^ b_swz[nj]) << 4);
                LDSM_X2(b0[nj], b1[nj], addr);
            }
#pragma unroll
            for (int mi = 0; mi < 4; ++mi)
#pragma unroll
                for (int nj = 0; nj < 4; ++nj)
                    MMA_16816(acc[mi][nj][0], acc[mi][nj][1],
                              acc[mi][nj][2], acc[mi][nj][3],
                              a0[mi], a1[mi], a2[mi], a3[mi],
                              b0[nj], b1[nj]);
        }
        __syncthreads();
    }

    // ---- epilogue: fp32 direct stores (float2 per lane per row-half)
    const int erow = (lane >> 2);
    const int ecol = (lane & 3) * 2;
#pragma unroll
    for (int mi = 0; mi < 4; ++mi) {
#pragma unroll
        for (int nj = 0; nj < 4; ++nj) {
            int row = bm + wm * 64 + mi * 16 + erow;
            int col = bn + wn * 32 + nj * 8 + ecol;
            float2 v0 = make_float2(acc[mi][nj][0], acc[mi][nj][1]);
            float2 v1 = make_float2(acc[mi][nj][2], acc[mi][nj][3]);
            *(float2*)(C + (size_t)row * PD + col)       = v0;
            *(float2*)(C + (size_t)(row + 8) * PD + col) = v1;
        }
    }
}

// ---------------------------------------------------------------------------
// RoPE tables (double-precision trig on fp32-rounded angle chain)
// ---------------------------------------------------------------------------
__global__ void rope_tables(float* __restrict__ ct, float* __restrict__ st)
{
    int idx = blockIdx.x * blockDim.x + threadIdx.x;
    if (idx >= PS * (PHD / 2)) return;
    int s = idx >> 6;
    int j = idx & 63;
    float invf = (float)pow(10000.0, -(double)j / 64.0);
    float ang  = (float)s * invf;
    double a   = (double)ang;
    ct[idx] = (float)cos(a);
    st[idx] = (float)sin(a);
}

// ---------------------------------------------------------------------------
// RoPE apply (in-place on Q and K, layout [B,S,H*HD])
// ---------------------------------------------------------------------------
__global__ __launch_bounds__(256)
void rope_apply(float* __restrict__ Q, float* __restrict__ Kv,
                const float* __restrict__ ct, const float* __restrict__ st)
{
    const int row = blockIdx.x;
    const int s   = row & (PS - 1);
    const int tid = threadIdx.x;
    __shared__ float buf[PD];

#pragma unroll
    for (int pass = 0; pass < 2; ++pass) {
        float* ptr = (pass == 0 ? Q : Kv) + (size_t)row * PD;
        for (int i = tid; i < PD; i += 256) buf[i] = ptr[i];
        __syncthreads();
        for (int i = tid; i < PD; i += 256) {
            int d = i & (PHD - 1);
            int j = d & 63;
            float c  = ct[s * 64 + j];
            float sn = st[s * 64 + j];
            float x  = buf[i];
            float xr = (d < 64) ? -buf[i + 64] : buf[i - 64];
            ptr[i] = fmaf(x, c, xr * sn);
        }
        __syncthreads();
    }
}

// ---------------------------------------------------------------------------
// Causal flash attention, fp32 (unchanged: known-correct)
// ---------------------------------------------------------------------------
#define AQP (PHD + 1)
#define APP 65
#define ATTN_SMEM ((3 * 64 * AQP + 64 * APP) * (int)sizeof(float))

__global__ __launch_bounds__(256)
void attn_fwd(const float* __restrict__ Q, const float* __restrict__ K,
              const float* __restrict__ V, float* __restrict__ O)
{
    extern __shared__ float smattn[];
    float* Qs = smattn;
    float* Ks = Qs + 64 * AQP;
    float* Vs = Ks + 64 * AQP;
    float* Ps = Vs + 64 * AQP;

    const int tid = threadIdx.x;
    const int tx  = tid & 15;
    const int ty  = tid >> 4;
    const int qt  = blockIdx.x;
    const int bh  = blockIdx.y;
    const int b   = bh >> 4;
    const int h   = bh & 15;
    const int qbase = qt * 64;

    const float scale = 0.08838834764831845f;

    const float* qg = Q + ((size_t)b * PS) * PD + (size_t)h * PHD;
    const float* kg = K + ((size_t)b * PS) * PD + (size_t)h * PHD;
    const float* vg = V + ((size_t)b * PS) * PD + (size_t)h * PHD;

    for (int i = tid; i < 64 * 32; i += 256) {
        int r = i >> 5;
        int c = (i & 31) << 2;
        float4 v = *(const float4*)(qg + (size_t)(qbase + r) * PD + c);
        float* dst = Qs + r * AQP + c;
        dst[0] = v.x; dst[1] = v.y; dst[2] = v.z; dst[3] = v.w;
    }

    float m[4], l[4], o[4][8];
#pragma unroll
    for (int ii = 0; ii < 4; ++ii) {
        m[ii] = -INFINITY;
        l[ii] = 0.0f;
#pragma unroll
        for (int jj = 0; jj < 8; ++jj) o[ii][jj] = 0.0f;
    }

    for (int kt = 0; kt <= qt; ++kt) {
        const int kbase = kt * 64;
        __syncthreads();
        for (int i = tid; i < 64 * 32; i += 256) {
            int r = i >> 5;
            int c = (i & 31) << 2;
            float4 vk = *(const float4*)(kg + (size_t)(kbase + r) * PD + c);
            float* dk = Ks + r * AQP + c;
            dk[0] = vk.x; dk[1] = vk.y; dk[2] = vk.z; dk[3] = vk.w;
            float4 vv = *(const float4*)(vg + (size_t)(kbase + r) * PD + c);
            float* dv = Vs + r * AQP + c;
            dv[0] = vv.x; dv[1] = vv.y; dv[2] = vv.z; dv[3] = vv.w;
        }
        __syncthreads();

        float sc[4][4];
#pragma unroll
        for (int ii = 0; ii < 4; ++ii)
#pragma unroll
            for (int jj = 0; jj < 4; ++jj) sc[ii][jj] = 0.0f;

        const float* q0 = Qs + (ty * 4) * AQP;
        const float* k0 = Ks + tx * AQP;
#pragma unroll 4
        for (int d = 0; d < PHD; ++d) {
            float av[4], bv[4];
            av[0] = q0[d];
            av[1] = q0[AQP + d];
            av[2] = q0[2 * AQP + d];
            av[3] = q0[3 * AQP + d];
            bv[0] = k0[d];
            bv[1] = k0[16 * AQP + d];
            bv[2] = k0[32 * AQP + d];
            bv[3] = k0[48 * AQP + d];
#pragma unroll
            for (int ii = 0; ii < 4; ++ii)
#pragma unroll
                for (int jj = 0; jj < 4; ++jj)
                    sc[ii][jj] = fmaf(av[ii], bv[jj], sc[ii][jj]);
        }

        if (kt == qt) {
#pragma unroll
            for (int ii = 0; ii < 4; ++ii) {
                const int qi = ty * 4 + ii;
#pragma unroll
                for (int jj = 0; jj < 4; ++jj) {
                    const int kj = jj * 16 + tx;
                    sc[ii][jj] = (kj <= qi) ? sc[ii][jj] * scale : -INFINITY;
                }
            }
        } else {
#pragma unroll
            for (int ii = 0; ii < 4; ++ii)
#pragma unroll
                for (int jj = 0; jj < 4; ++jj) sc[ii][jj] *= scale;
        }

#pragma unroll
        for (int ii = 0; ii < 4; ++ii) {
            float rm = fmaxf(fmaxf(sc[ii][0], sc[ii][1]),
                             fmaxf(sc[ii][2], sc[ii][3]));
#pragma unroll
            for (int off = 8; off >= 1; off >>= 1)
                rm = fmaxf(rm, __shfl_xor_sync(0xffffffffu, rm, off));
            float mn = fmaxf(m[ii], rm);
            float p0 = __expf(sc[ii][0] - mn);
            float p1 = __expf(sc[ii][1] - mn);
            float p2 = __expf(sc[ii][2] - mn);
            float p3 = __expf(sc[ii][3] - mn);
            float rs = (p0 + p1) + (p2 + p3);
#pragma unroll
            for (int off = 8; off >= 1; off >>= 1)
                rs += __shfl_xor_sync(0xffffffffu, rs, off);
            float corr = __expf(m[ii] - mn);
            m[ii] = mn;
            l[ii] = l[ii] * corr + rs;
#pragma unroll
            for (int jj = 0; jj < 8; ++jj) o[ii][jj] *= corr;
            float* prow = Ps + (ty * 4 + ii) * APP;
            prow[tx]      = p0;
            prow[16 + tx] = p1;
            prow[32 + tx] = p2;
            prow[48 + tx] = p3;
        }
        __syncthreads();

#pragma unroll 2
        for (int j = 0; j < 64; ++j) {
            float pv[4];
#pragma unroll
            for (int ii = 0; ii < 4; ++ii)
                pv[ii] = Ps[(ty * 4 + ii) * APP + j];
            const float* vj = Vs + j * AQP + tx;
#pragma unroll
            for (int jj = 0; jj < 8; ++jj) {
                float vvv = vj[jj * 16];
#pragma unroll
                for (int ii = 0; ii < 4; ++ii)
                    o[ii][jj] = fmaf(pv[ii], vvv, o[ii][jj]);
            }
        }
    }

#pragma unroll
    for (int ii = 0; ii < 4; ++ii) {
        float inv = 1.0f / l[ii];
        float* orow = O + ((size_t)b * PS + qbase + ty * 4 + ii) * PD
                        + (size_t)h * PHD + tx;
#pragma unroll
        for (int jj = 0; jj < 8; ++jj)
            orow[jj * 16] = o[ii][jj] * inv;
    }
}

// ---------------------------------------------------------------------------
// kernel_launch
// ---------------------------------------------------------------------------
extern "C" void kernel_launch(void* const* d_in, const int* in_sizes, int n_in,
                              void* d_out, int out_size)
{
    const float* x  = (const float*)d_in[0];
    const float* Wq = (const float*)d_in[1];
    const float* Wk = (const float*)d_in[2];
    const float* Wv = (const float*)d_in[3];
    const float* Wo = (const float*)d_in[4];
    float* out = (float*)d_out;

    float *Qp, *Kp, *Vp, *AOp, *cp, *sp;
    __nv_bfloat16 *Axp, *Bqp, *Bkp, *Bvp, *Bop;
    cudaGetSymbolAddress((void**)&Qp,  g_Q);
    cudaGetSymbolAddress((void**)&Kp,  g_K);
    cudaGetSymbolAddress((void**)&Vp,  g_V);
    cudaGetSymbolAddress((void**)&AOp, g_AO);
    cudaGetSymbolAddress((void**)&cp,  g_cos);
    cudaGetSymbolAddress((void**)&sp,  g_sin);
    cudaGetSymbolAddress((void**)&Axp, g_Ax);
    cudaGetSymbolAddress((void**)&Bqp, g_Bq);
    cudaGetSymbolAddress((void**)&Bkp, g_Bk);
    cudaGetSymbolAddress((void**)&Bvp, g_Bv);
    cudaGetSymbolAddress((void**)&Bop, g_Bo);

    cudaFuncSetAttribute(attn_fwd,  cudaFuncAttributeMaxDynamicSharedMemorySize, ATTN_SMEM);
    cudaFuncSetAttribute(gemm_hmma, cudaFuncAttributeMaxDynamicSharedMemorySize, HG_SMEM);

    const int wpairs = PD * PD / 2;
    const int xpairs = PM * PD / 2;

    // weight + activation splits
    split3<<<(wpairs + 255) / 256, 256>>>(Wq, Bqp, 1, wpairs);
    split3<<<(wpairs + 255) / 256, 256>>>(Wk, Bkp, 1, wpairs);
    split3<<<(wpairs + 255) / 256, 256>>>(Wv, Bvp, 1, wpairs);
    split3<<<(wpairs + 255) / 256, 256>>>(Wo, Bop, 1, wpairs);
    split3<<<(xpairs + 255) / 256, 256>>>(x,  Axp, 0, xpairs);

    dim3 ggrid(PD / HG_BN, PM / HG_BM);   // (16, 32)

    // Q/K/V projections on HMMA tensor cores
    gemm_hmma<<<ggrid, 256, HG_SMEM>>>(Axp, Bqp, Qp);
    gemm_hmma<<<ggrid, 256, HG_SMEM>>>(Axp, Bkp, Kp);
    gemm_hmma<<<ggrid, 256, HG_SMEM>>>(Axp, Bvp, Vp);

    // RoPE
    rope_tables<<<(PS * 64 + 255) / 256, 256>>>(cp, sp);
    rope_apply<<<PM, 256>>>(Qp, Kp, cp, sp);

    // causal flash attention (fp32)
    attn_fwd<<<dim3(PS / 64, PB * PH), 256, ATTN_SMEM>>>(Qp, Kp, Vp, AOp);

    // output projection
    split3<<<(xpairs + 255) / 256, 256>>>(AOp, Axp, 0, xpairs);
    gemm_hmma<<<ggrid, 256, HG_SMEM>>>(Axp, Bop, out);
}

// round 4
// speedup vs baseline: 2.6402x; 1.4784x over previous
#include <cuda_runtime.h>
#include <cuda_bf16.h>
#include <math.h>
#include <stdint.h>

// ---------------------------------------------------------------------------
// Problem constants
// ---------------------------------------------------------------------------
#define PB 2
#define PS 2048
#define PD 2048
#define PH 16
#define PHD 128
#define PM (PB * PS)          // 4096 rows
#define K3 (3 * PD)           // 6144: split-K for bf16x3
#define ATT_SCALE 0.08838834764831845f

// ---------------------------------------------------------------------------
// Scratch (device globals; no allocation allowed)
// ---------------------------------------------------------------------------
__device__ float g_Q[(size_t)PM * PD];
__device__ float g_K[(size_t)PM * PD];
__device__ float g_cos[PS * (PHD / 2)];
__device__ float g_sin[PS * (PHD / 2)];
__device__ __nv_bfloat16 g_Ax[(size_t)PM * K3];          // split activations
__device__ __nv_bfloat16 g_Bq[(size_t)PD * K3];
__device__ __nv_bfloat16 g_Bk[(size_t)PD * K3];
__device__ __nv_bfloat16 g_Bv[(size_t)PD * K3];
__device__ __nv_bfloat16 g_Bo[(size_t)PD * K3];
__device__ __nv_bfloat16 g_Q3[(size_t)PB * PH * PS * 384];   // [qh|qh|ql]*scale
__device__ __nv_bfloat16 g_K3[(size_t)PB * PH * PS * 384];   // [kh|kl|kh]
__device__ __nv_bfloat16 g_Vh[(size_t)PB * PH * PS * PHD];
__device__ __nv_bfloat16 g_Vl[(size_t)PB * PH * PS * PHD];

// ---------------------------------------------------------------------------
// PTX helpers (sm_80-compatible: cp.async + ldmatrix + mma.sync)
// ---------------------------------------------------------------------------
__device__ __forceinline__ uint32_t smem_u32(const void* p) {
    uint32_t a;
    asm("{ .reg .u64 t; cvta.to.shared.u64 t, %1; cvt.u32.u64 %0, t; }"
        : "=r"(a) : "l"(p));
    return a;
}

#define CP_ASYNC16(smem, gptr) \
    asm volatile("cp.async.cg.shared.global [%0], [%1], 16;" \
                 :: "r"(smem), "l"(gptr) : "memory")
#define CP_COMMIT() asm volatile("cp.async.commit_group;" ::: "memory")
#define CP_WAIT2()  asm volatile("cp.async.wait_group 2;" ::: "memory")
#define CP_WAIT0()  asm volatile("cp.async.wait_group 0;" ::: "memory")

#define LDSM_X4(r0, r1, r2, r3, addr) \
    asm volatile("ldmatrix.sync.aligned.m8n8.x4.shared.b16 {%0,%1,%2,%3}, [%4];" \
                 : "=r"(r0), "=r"(r1), "=r"(r2), "=r"(r3) : "r"(addr))
#define LDSM_X4T(r0, r1, r2, r3, addr) \
    asm volatile("ldmatrix.sync.aligned.m8n8.x4.trans.shared.b16 {%0,%1,%2,%3}, [%4];" \
                 : "=r"(r0), "=r"(r1), "=r"(r2), "=r"(r3) : "r"(addr))
#define LDSM_X2(r0, r1, addr) \
    asm volatile("ldmatrix.sync.aligned.m8n8.x2.shared.b16 {%0,%1}, [%2];" \
                 : "=r"(r0), "=r"(r1) : "r"(addr))

#define MMA_16816(c0, c1, c2, c3, a0, a1, a2, a3, b0, b1) \
    asm volatile("mma.sync.aligned.m16n8k16.row.col.f32.bf16.bf16.f32 " \
                 "{%0,%1,%2,%3}, {%4,%5,%6,%7}, {%8,%9}, {%0,%1,%2,%3};" \
                 : "+f"(c0), "+f"(c1), "+f"(c2), "+f"(c3) \
                 : "r"(a0), "r"(a1), "r"(a2), "r"(a3), "r"(b0), "r"(b1))

// swizzles
__device__ __forceinline__ uint32_t swz64(int r, int ch) {   // 64B rows, 4x16B chunks
    return (uint32_t)(r * 64 + (((ch) ^ ((r >> 1) & 3)) << 4));
}
__device__ __forceinline__ uint32_t swzV(int r, int ch) {    // 256B rows, 16x16B chunks
    return (uint32_t)(r * 256 + (((ch) ^ (r & 7)) << 4));
}

// ---------------------------------------------------------------------------
// Split fp32 -> 3-segment bf16: order=0 (activations): [hi | hi | lo]
//                               order=1 (weights):     [hi | lo | hi]
// ---------------------------------------------------------------------------
__global__ void split3(const float* __restrict__ X, __nv_bfloat16* __restrict__ Y,
                       int order, int npairs)
{
    int i = blockIdx.x * blockDim.x + threadIdx.x;
    if (i >= npairs) return;
    int r = i >> 10;
    int c = (i & 1023) << 1;
    float2 v = *(const float2*)(X + (size_t)r * PD + c);
    __nv_bfloat16 h0 = __float2bfloat16(v.x);
    __nv_bfloat16 h1 = __float2bfloat16(v.y);
    __nv_bfloat16 l0 = __float2bfloat16(v.x - __bfloat162float(h0));
    __nv_bfloat16 l1 = __float2bfloat16(v.y - __bfloat162float(h1));
    __nv_bfloat162 hh = __halves2bfloat162(h0, h1);
    __nv_bfloat162 ll = __halves2bfloat162(l0, l1);
    __nv_bfloat162* base = (__nv_bfloat162*)(Y + (size_t)r * K3 + c);
    base[0]    = hh;
    base[1024] = order ? ll : hh;
    base[2048] = order ? hh : ll;
}

// ---------------------------------------------------------------------------
// HMMA bf16 GEMM (proven round-3 body), templated epilogue:
//  MODE 0: fp32 C stores
//  MODE 1: V head-split -> Vh/Vl bf16 [b,h,s,128]
// ---------------------------------------------------------------------------
#define HG_BM 128
#define HG_BN 128
#define HG_BK 32
#define HG_STG 4
#define HG_STAGE_BYTES 16384
#define HG_SMEM (HG_STG * HG_STAGE_BYTES)
#define HG_KT (K3 / HG_BK)

template<int MODE>
__global__ __launch_bounds__(256, 2)
void gemm_hmma(const __nv_bfloat16* __restrict__ A3,
               const __nv_bfloat16* __restrict__ B3,
               float* __restrict__ C,
               __nv_bfloat16* __restrict__ Vho,
               __nv_bfloat16* __restrict__ Vlo)
{
    extern __shared__ __align__(1024) char smem[];
    const uint32_t sbase = smem_u32(smem);

    const int tid  = threadIdx.x;
    const int lane = tid & 31;
    const int wid  = tid >> 5;
    const int wm   = wid & 1;
    const int wn   = wid >> 1;
    const int bm   = blockIdx.y * HG_BM;
    const int bn   = blockIdx.x * HG_BN;

    const __nv_bfloat16* Ag = A3 + (size_t)bm * K3;
    const __nv_bfloat16* Bg = B3 + (size_t)bn * K3;

    int lr[2], lc[2];
    uint32_t lsw[2];
    const __nv_bfloat16* gA[2];
    const __nv_bfloat16* gB[2];
#pragma unroll
    for (int p = 0; p < 2; ++p) {
        int idx = tid + p * 256;
        lr[p] = idx >> 2;
        lc[p] = idx & 3;
        lsw[p] = swz64(lr[p], lc[p]);
        gA[p] = Ag + (size_t)lr[p] * K3 + lc[p] * 8;
        gB[p] = Bg + (size_t)lr[p] * K3 + lc[p] * 8;
    }

    uint32_t a_row_off[4];
    int a_swz[4];
#pragma unroll
    for (int mi = 0; mi < 4; ++mi) {
        int r = wm * 64 + mi * 16 + (lane & 15);
        a_row_off[mi] = (uint32_t)(r * 64);
        a_swz[mi] = (r >> 1) & 3;
    }
    const int a_cpart = lane >> 4;
    uint32_t b_row_off[4];
    int b_swz[4];
#pragma unroll
    for (int nj = 0; nj < 4; ++nj) {
        int r = wn * 32 + nj * 8 + (lane & 7);
        b_row_off[nj] = (uint32_t)(r * 64);
        b_swz[nj] = (r >> 1) & 3;
    }
    const int b_cpart = (lane >> 3) & 1;

    float acc[4][4][4];
#pragma unroll
    for (int mi = 0; mi < 4; ++mi)
#pragma unroll
        for (int nj = 0; nj < 4; ++nj)
#pragma unroll
            for (int e = 0; e < 4; ++e) acc[mi][nj][e] = 0.0f;

#pragma unroll
    for (int s = 0; s < HG_STG - 1; ++s) {
        uint32_t sA = sbase + s * HG_STAGE_BYTES;
        uint32_t sB = sA + 8192;
        int k0 = s * HG_BK;
#pragma unroll
        for (int p = 0; p < 2; ++p) {
            CP_ASYNC16(sA + lsw[p], gA[p] + k0);
            CP_ASYNC16(sB + lsw[p], gB[p] + k0);
        }
        CP_COMMIT();
    }

    for (int kt = 0; kt < HG_KT; ++kt) {
        CP_WAIT2();
        __syncthreads();

        int nk = kt + HG_STG - 1;
        if (nk < HG_KT) {
            uint32_t sA = sbase + (nk & 3) * HG_STAGE_BYTES;
            uint32_t sB = sA + 8192;
            int k0 = nk * HG_BK;
#pragma unroll
            for (int p = 0; p < 2; ++p) {
                CP_ASYNC16(sA + lsw[p], gA[p] + k0);
                CP_ASYNC16(sB + lsw[p], gB[p] + k0);
            }
        }
        CP_COMMIT();

        uint32_t sA = sbase + (kt & 3) * HG_STAGE_BYTES;
        uint32_t sB = sA + 8192;
#pragma unroll
        for (int h = 0; h < 2; ++h) {
            uint32_t a0[4], a1[4], a2[4], a3[4];
#pragma unroll
            for (int mi = 0; mi < 4; ++mi) {
                uint32_t addr = sA + a_row_off[mi]
                              + (uint32_t)(((2 * h + a_cpart) ^ a_swz[mi]) << 4);
                LDSM_X4(a0[mi], a1[mi], a2[mi], a3[mi], addr);
            }
            uint32_t b0[4], b1[4];
#pragma unroll
            for (int nj = 0; nj < 4; ++nj) {
                uint32_t addr = sB + b_row_off[nj]
                              + (uint32_t)(((2 * h + b_cpart) ^ b_swz[nj]) << 4);
                LDSM_X2(b0[nj], b1[nj], addr);
            }
#pragma unroll
            for (int mi = 0; mi < 4; ++mi)
#pragma unroll
                for (int nj = 0; nj < 4; ++nj)
                    MMA_16816(acc[mi][nj][0], acc[mi][nj][1],
                              acc[mi][nj][2], acc[mi][nj][3],
                              a0[mi], a1[mi], a2[mi], a3[mi],
                              b0[nj], b1[nj]);
        }
        __syncthreads();
    }

    const int erow = (lane >> 2);
    const int ecol = (lane & 3) * 2;
#pragma unroll
    for (int mi = 0; mi < 4; ++mi) {
#pragma unroll
        for (int nj = 0; nj < 4; ++nj) {
            int row = bm + wm * 64 + mi * 16 + erow;
            int col = bn + wn * 32 + nj * 8 + ecol;
            if (MODE == 0) {
                float2 v0 = make_float2(acc[mi][nj][0], acc[mi][nj][1]);
                float2 v1 = make_float2(acc[mi][nj][2], acc[mi][nj][3]);
                *(float2*)(C + (size_t)row * PD + col)       = v0;
                *(float2*)(C + (size_t)(row + 8) * PD + col) = v1;
            } else {
                int b = row >> 11, s = row & 2047;
                int h = col >> 7, hd = col & 127;
                size_t dst = ((size_t)(b * PH + h) * PS + s) * PHD + hd;
                float2 p0 = make_float2(acc[mi][nj][0], acc[mi][nj][1]);
                float2 p1 = make_float2(acc[mi][nj][2], acc[mi][nj][3]);
                __nv_bfloat162 h20 = __float22bfloat162_rn(p0);
                __nv_bfloat162 h21 = __float22bfloat162_rn(p1);
                float2 r0 = make_float2(p0.x - __bfloat162float(h20.x),
                                        p0.y - __bfloat162float(h20.y));
                float2 r1 = make_float2(p1.x - __bfloat162float(h21.x),
                                        p1.y - __bfloat162float(h21.y));
                *(__nv_bfloat162*)(Vho + dst)            = h20;
                *(__nv_bfloat162*)(Vho + dst + 8 * PHD)  = h21;
                *(__nv_bfloat162*)(Vlo + dst)            = __float22bfloat162_rn(r0);
                *(__nv_bfloat162*)(Vlo + dst + 8 * PHD)  = __float22bfloat162_rn(r1);
            }
        }
    }
}

// ---------------------------------------------------------------------------
// RoPE tables (fp64 trig on fp32-rounded angle chain)
// ---------------------------------------------------------------------------
__global__ void rope_tables(float* __restrict__ ct, float* __restrict__ st)
{
    int idx = blockIdx.x * blockDim.x + threadIdx.x;
    if (idx >= PS * (PHD / 2)) return;
    int s = idx >> 6;
    int j = idx & 63;
    float invf = (float)pow(10000.0, -(double)j / 64.0);
    float ang  = (float)s * invf;
    double a   = (double)ang;
    ct[idx] = (float)cos(a);
    st[idx] = (float)sin(a);
}

// ---------------------------------------------------------------------------
// RoPE + scale + split: Q,K fp32 [b*s][2048] -> Q3 ([qh|qh|ql]*scale),
// K3 ([kh|kl|kh]); layout [b,h,s,384].
// ---------------------------------------------------------------------------
__global__ __launch_bounds__(256)
void rope_split(const float* __restrict__ Q, const float* __restrict__ Kf,
                const float* __restrict__ ct, const float* __restrict__ st,
                __nv_bfloat16* __restrict__ Q3, __nv_bfloat16* __restrict__ K3g)
{
    const int row = blockIdx.x;           // b*S + s
    const int b   = row >> 11;
    const int s   = row & (PS - 1);
    const int tid = threadIdx.x;
    __shared__ float buf[PD];

#pragma unroll
    for (int pass = 0; pass < 2; ++pass) {
        const float* src = (pass == 0 ? Q : Kf) + (size_t)row * PD;
        __nv_bfloat16* dstbase = pass == 0 ? Q3 : K3g;
        for (int i = tid; i < PD; i += 256) buf[i] = src[i];
        __syncthreads();
        for (int i = tid; i < PD; i += 256) {
            int d = i & (PHD - 1);
            int h = i >> 7;
            int j = d & 63;
            float c  = ct[s * 64 + j];
            float sn = st[s * 64 + j];
            float x  = buf[i];
            float xr = (d < 64) ? -buf[i + 64] : buf[i - 64];
            float val = fmaf(x, c, xr * sn);
            if (pass == 0) val *= ATT_SCALE;
            __nv_bfloat16 hi = __float2bfloat16(val);
            __nv_bfloat16 lo = __float2bfloat16(val - __bfloat162float(hi));
            __nv_bfloat16* out = dstbase
                + ((size_t)(b * PH + h) * PS + s) * 384 + d;
            if (pass == 0) { out[0] = hi; out[128] = hi; out[256] = lo; }
            else           { out[0] = hi; out[128] = lo; out[256] = hi; }
        }
        __syncthreads();
    }
}

// ---------------------------------------------------------------------------
// Tensor-core causal flash attention.
// CTA: 128 queries, 8 warps x 16 rows. Key tiles of 64.
// QK: K'=384 (3-term); PV: 3 passes (ph*vh, pl*vh, ph*vl).
// Output written directly as [hi|hi|lo] split into AX for the Wo GEMM.
// ---------------------------------------------------------------------------
#define ATS_Q  0
#define ATS_K  98304
#define ATS_VH 147456
#define ATS_VL 163840
#define ATS_P  180224
#define ATT_SMEM 212992

__global__ __launch_bounds__(256, 1)
void attn_tc(const __nv_bfloat16* __restrict__ Q3,
             const __nv_bfloat16* __restrict__ K3g,
             const __nv_bfloat16* __restrict__ Vh,
             const __nv_bfloat16* __restrict__ Vl,
             __nv_bfloat16* __restrict__ AX)
{
    extern __shared__ __align__(1024) char sm[];
    const uint32_t sb = smem_u32(sm);
    const int tid  = threadIdx.x;
    const int lane = tid & 31;
    const int w    = tid >> 5;
    const int qt   = 15 - (int)blockIdx.x;   // long tiles first
    const int bh   = blockIdx.y;
    const int qb   = qt * 128;
    const int nkt  = 2 * qt + 2;

    const __nv_bfloat16* q3 = Q3 + ((size_t)bh * PS + qb) * 384;
    const __nv_bfloat16* k3 = K3g + (size_t)bh * PS * 384;
    const __nv_bfloat16* vh = Vh + (size_t)bh * PS * PHD;
    const __nv_bfloat16* vl = Vl + (size_t)bh * PS * PHD;

    // ---- Q tile (128 x 384) via cp.async
#pragma unroll
    for (int p = 0; p < 12; ++p)
#pragma unroll
        for (int ps = 0; ps < 2; ++ps) {
            int idx = tid + ps * 256;
            int r = idx >> 2, ch = idx & 3;
            CP_ASYNC16(sb + ATS_Q + p * 8192 + swz64(r, ch),
                       q3 + (size_t)r * 384 + p * 32 + ch * 8);
        }
    // ---- K0, V0
    {
        const __nv_bfloat16* kp = k3;
        int r = tid >> 2, ch = tid & 3;
#pragma unroll
        for (int p = 0; p < 12; ++p)
            CP_ASYNC16(sb + ATS_K + p * 4096 + swz64(r, ch),
                       kp + (size_t)r * 384 + p * 32 + ch * 8);
#pragma unroll
        for (int ps = 0; ps < 4; ++ps) {
            int idx = tid + ps * 256;
            int rr = idx >> 4, cc = idx & 15;
            CP_ASYNC16(sb + ATS_VH + swzV(rr, cc), vh + (size_t)rr * PHD + cc * 8);
            CP_ASYNC16(sb + ATS_VL + swzV(rr, cc), vl + (size_t)rr * PHD + cc * 8);
        }
    }
    CP_COMMIT();

    float m0 = -INFINITY, m1 = -INFINITY, l0 = 0.0f, l1 = 0.0f;
    float oa[16][4];
#pragma unroll
    for (int j = 0; j < 16; ++j)
#pragma unroll
        for (int e = 0; e < 4; ++e) oa[j][e] = 0.0f;

    const int arow  = w * 16 + (lane & 15);
    const int aswz  = (arow >> 1) & 3;
    const int acp   = lane >> 4;
    const int rr0   = w * 16 + (lane >> 2);       // this lane's row (c0,c1)
    const int prow0 = rr0;
    const int prow1 = rr0 + 8;
    const int pswz0 = (prow0 >> 1) & 3;
    const int pswz1 = (prow1 >> 1) & 3;
    const int vkrow_base = (lane & 7) + 8 * ((lane >> 3) & 1);

    for (int kt = 0; kt < nkt; ++kt) {
        CP_WAIT0();
        __syncthreads();

        // ================= QK: S[16 x 64] per warp, K'=384 =================
        float sa[8][4];
#pragma unroll
        for (int j = 0; j < 8; ++j)
#pragma unroll
            for (int e = 0; e < 4; ++e) sa[j][e] = 0.0f;

#pragma unroll
        for (int p = 0; p < 12; ++p) {
#pragma unroll
            for (int h = 0; h < 2; ++h) {
                uint32_t a0, a1, a2, a3;
                LDSM_X4(a0, a1, a2, a3,
                        sb + ATS_Q + p * 8192 + arow * 64
                           + (((2 * h + acp) ^ aswz) << 4));
#pragma unroll
                for (int jj = 0; jj < 4; ++jj) {
                    int brow = jj * 16 + (lane & 15);
                    uint32_t b0, b1, b2, b3;
                    LDSM_X4(b0, b1, b2, b3,
                            sb + ATS_K + p * 4096 + brow * 64
                               + (((2 * h + acp) ^ ((brow >> 1) & 3)) << 4));
                    MMA_16816(sa[2 * jj][0], sa[2 * jj][1], sa[2 * jj][2], sa[2 * jj][3],
                              a0, a1, a2, a3, b0, b2);
                    MMA_16816(sa[2 * jj + 1][0], sa[2 * jj + 1][1],
                              sa[2 * jj + 1][2], sa[2 * jj + 1][3],
                              a0, a1, a2, a3, b1, b3);
                }
            }
        }
        __syncthreads();

        // prefetch next K under softmax+PV
        if (kt + 1 < nkt) {
            const __nv_bfloat16* kp = k3 + (size_t)(kt + 1) * 64 * 384;
            int r = tid >> 2, ch = tid & 3;
#pragma unroll
            for (int p = 0; p < 12; ++p)
                CP_ASYNC16(sb + ATS_K + p * 4096 + swz64(r, ch),
                           kp + (size_t)r * 384 + p * 32 + ch * 8);
        }
        CP_COMMIT();

        // ================= online softmax =================
        const int kb = kt * 64;
        if (kt >= 2 * qt) {          // diagonal tiles: causal mask
            const int rg0 = qb + rr0;
            const int rg1 = rg0 + 8;
#pragma unroll
            for (int j = 0; j < 8; ++j) {
                int c0 = kb + j * 8 + 2 * (lane & 3);
                if (c0 > rg0)     sa[j][0] = -INFINITY;
                if (c0 + 1 > rg0) sa[j][1] = -INFINITY;
                if (c0 > rg1)     sa[j][2] = -INFINITY;
                if (c0 + 1 > rg1) sa[j][3] = -INFINITY;
            }
        }
        float rmax0 = -INFINITY, rmax1 = -INFINITY;
#pragma unroll
        for (int j = 0; j < 8; ++j) {
            rmax0 = fmaxf(rmax0, fmaxf(sa[j][0], sa[j][1]));
            rmax1 = fmaxf(rmax1, fmaxf(sa[j][2], sa[j][3]));
        }
        rmax0 = fmaxf(rmax0, __shfl_xor_sync(0xffffffffu, rmax0, 1));
        rmax0 = fmaxf(rmax0, __shfl_xor_sync(0xffffffffu, rmax0, 2));
        rmax1 = fmaxf(rmax1, __shfl_xor_sync(0xffffffffu, rmax1, 1));
        rmax1 = fmaxf(rmax1, __shfl_xor_sync(0xffffffffu, rmax1, 2));

        float mn0 = fmaxf(m0, rmax0);
        float mn1 = fmaxf(m1, rmax1);
        float corr0 = __expf(m0 - mn0);
        float corr1 = __expf(m1 - mn1);
        m0 = mn0; m1 = mn1;
#pragma unroll
        for (int j = 0; j < 16; ++j) {
            oa[j][0] *= corr0; oa[j][1] *= corr0;
            oa[j][2] *= corr1; oa[j][3] *= corr1;
        }
        float rs0 = 0.0f, rs1 = 0.0f;
#pragma unroll
        for (int j = 0; j < 8; ++j) {
            float p0 = __expf(sa[j][0] - mn0);
            float p1 = __expf(sa[j][1] - mn0);
            float p2 = __expf(sa[j][2] - mn1);
            float p3 = __expf(sa[j][3] - mn1);
            rs0 += p0 + p1;
            rs1 += p2 + p3;
            // write [ph | pl] into P panels
            int key = j * 8 + 2 * (lane & 3);
            int panel = key >> 5, kin = key & 31;
            uint32_t inoff = (uint32_t)(((kin >> 3)) << 4) + ((kin & 7) << 1);
            __nv_bfloat162 h2a = __float22bfloat162_rn(make_float2(p0, p1));
            __nv_bfloat162 h2b = __float22bfloat162_rn(make_float2(p2, p3));
            __nv_bfloat162 l2a = __float22bfloat162_rn(make_float2(
                p0 - __bfloat162float(h2a.x), p1 - __bfloat162float(h2a.y)));
            __nv_bfloat162 l2b = __float22bfloat162_rn(make_float2(
                p2 - __bfloat162float(h2b.x), p3 - __bfloat162float(h2b.y)));
            uint32_t ba0 = (uint32_t)(ATS_P + panel * 8192) + prow0 * 64
                         + ((inoff & 0xF0u) ^ (pswz0 << 4)) + (inoff & 0xFu);
            uint32_t ba1 = (uint32_t)(ATS_P + panel * 8192) + prow1 * 64
                         + ((inoff & 0xF0u) ^ (pswz1 << 4)) + (inoff & 0xFu);
            *(__nv_bfloat162*)(sm + ba0)             = h2a;
            *(__nv_bfloat162*)(sm + ba1)             = h2b;
            *(__nv_bfloat162*)(sm + ba0 + 2 * 8192)  = l2a;
            *(__nv_bfloat162*)(sm + ba1 + 2 * 8192)  = l2b;
        }
        rs0 += __shfl_xor_sync(0xffffffffu, rs0, 1);
        rs0 += __shfl_xor_sync(0xffffffffu, rs0, 2);
        rs1 += __shfl_xor_sync(0xffffffffu, rs1, 1);
        rs1 += __shfl_xor_sync(0xffffffffu, rs1, 2);
        l0 = l0 * corr0 + rs0;
        l1 = l1 * corr1 + rs1;
        __syncwarp();

        // ================= PV: O += [ph|pl|ph] x [vh|vh|vl] =================
#pragma unroll
        for (int term = 0; term < 3; ++term) {
            const int ppan = (term == 1) ? 2 : 0;
            const uint32_t vbase = (term == 2) ? ATS_VL : ATS_VH;
#pragma unroll
            for (int s = 0; s < 4; ++s) {
                uint32_t a0, a1, a2, a3;
                LDSM_X4(a0, a1, a2, a3,
                        sb + ATS_P + (ppan + (s >> 1)) * 8192 + arow * 64
                           + (((2 * (s & 1) + acp) ^ aswz) << 4));
                int vk = s * 16 + vkrow_base;
#pragma unroll
                for (int g = 0; g < 8; ++g) {
                    uint32_t b0, b1, b2, b3;
                    LDSM_X4T(b0, b1, b2, b3,
                             sb + vbase + vk * 256
                                + ((((2 * g + (lane >> 4)) ^ (vk & 7))) << 4));
                    MMA_16816(oa[2 * g][0], oa[2 * g][1], oa[2 * g][2], oa[2 * g][3],
                              a0, a1, a2, a3, b0, b1);
                    MMA_16816(oa[2 * g + 1][0], oa[2 * g + 1][1],
                              oa[2 * g + 1][2], oa[2 * g + 1][3],
                              a0, a1, a2, a3, b2, b3);
                }
            }
        }
        __syncthreads();

        // prefetch next V
        if (kt + 1 < nkt) {
            const __nv_bfloat16* va = vh + (size_t)(kt + 1) * 64 * PHD;
            const __nv_bfloat16* vb = vl + (size_t)(kt + 1) * 64 * PHD;
#pragma unroll
            for (int ps = 0; ps < 4; ++ps) {
                int idx = tid + ps * 256;
                int rr = idx >> 4, cc = idx & 15;
                CP_ASYNC16(sb + ATS_VH + swzV(rr, cc), va + (size_t)rr * PHD + cc * 8);
                CP_ASYNC16(sb + ATS_VL + swzV(rr, cc), vb + (size_t)rr * PHD + cc * 8);
            }
        }
        CP_COMMIT();
    }

    // ================= epilogue: write [hi|hi|lo] split into AX =================
    const float inv0 = 1.0f / l0;
    const float inv1 = 1.0f / l1;
    const int b = bh >> 4, h = bh & 15;
    const size_t row0 = (size_t)b * PS + qb + rr0;
    const size_t row1 = row0 + 8;
#pragma unroll
    for (int j = 0; j < 16; ++j) {
        int col = h * PHD + j * 8 + 2 * (lane & 3);
        float2 p0 = make_float2(oa[j][0] * inv0, oa[j][1] * inv0);
        float2 p1 = make_float2(oa[j][2] * inv1, oa[j][3] * inv1);
        __nv_bfloat162 h20 = __float22bfloat162_rn(p0);
        __nv_bfloat162 h21 = __float22bfloat162_rn(p1);
        __nv_bfloat162 l20 = __float22bfloat162_rn(make_float2(
            p0.x - __bfloat162float(h20.x), p0.y - __bfloat162float(h20.y)));
        __nv_bfloat162 l21 = __float22bfloat162_rn(make_float2(
            p1.x - __bfloat162float(h21.x), p1.y - __bfloat162float(h21.y)));
        __nv_bfloat16* d0 = AX + row0 * K3 + col;
        __nv_bfloat16* d1 = AX + row1 * K3 + col;
        *(__nv_bfloat162*)(d0)        = h20;
        *(__nv_bfloat162*)(d0 + 2048) = h20;
        *(__nv_bfloat162*)(d0 + 4096) = l20;
        *(__nv_bfloat162*)(d1)        = h21;
        *(__nv_bfloat162*)(d1 + 2048) = h21;
        *(__nv_bfloat162*)(d1 + 4096) = l21;
    }
}

// ---------------------------------------------------------------------------
// kernel_launch
// ---------------------------------------------------------------------------
extern "C" void kernel_launch(void* const* d_in, const int* in_sizes, int n_in,
                              void* d_out, int out_size)
{
    const float* x  = (const float*)d_in[0];
    const float* Wq = (const float*)d_in[1];
    const float* Wk = (const float*)d_in[2];
    const float* Wv = (const float*)d_in[3];
    const float* Wo = (const float*)d_in[4];
    float* out = (float*)d_out;

    float *Qp, *Kp, *cp, *sp;
    __nv_bfloat16 *Axp, *Bqp, *Bkp, *Bvp, *Bop, *Q3p, *K3p, *Vhp, *Vlp;
    cudaGetSymbolAddress((void**)&Qp,  g_Q);
    cudaGetSymbolAddress((void**)&Kp,  g_K);
    cudaGetSymbolAddress((void**)&cp,  g_cos);
    cudaGetSymbolAddress((void**)&sp,  g_sin);
    cudaGetSymbolAddress((void**)&Axp, g_Ax);
    cudaGetSymbolAddress((void**)&Bqp, g_Bq);
    cudaGetSymbolAddress((void**)&Bkp, g_Bk);
    cudaGetSymbolAddress((void**)&Bvp, g_Bv);
    cudaGetSymbolAddress((void**)&Bop, g_Bo);
    cudaGetSymbolAddress((void**)&Q3p, g_Q3);
    cudaGetSymbolAddress((void**)&K3p, g_K3);
    cudaGetSymbolAddress((void**)&Vhp, g_Vh);
    cudaGetSymbolAddress((void**)&Vlp, g_Vl);

    cudaFuncSetAttribute(gemm_hmma<0>, cudaFuncAttributeMaxDynamicSharedMemorySize, HG_SMEM);
    cudaFuncSetAttribute(gemm_hmma<1>, cudaFuncAttributeMaxDynamicSharedMemorySize, HG_SMEM);
    cudaFuncSetAttribute(attn_tc, cudaFuncAttributeMaxDynamicSharedMemorySize, ATT_SMEM);

    const int wpairs = PD * PD / 2;
    const int xpairs = PM * PD / 2;

    split3<<<(wpairs + 255) / 256, 256>>>(Wq, Bqp, 1, wpairs);
    split3<<<(wpairs + 255) / 256, 256>>>(Wk, Bkp, 1, wpairs);
    split3<<<(wpairs + 255) / 256, 256>>>(Wv, Bvp, 1, wpairs);
    split3<<<(wpairs + 255) / 256, 256>>>(Wo, Bop, 1, wpairs);
    split3<<<(xpairs + 255) / 256, 256>>>(x,  Axp, 0, xpairs);

    dim3 ggrid(PD / HG_BN, PM / HG_BM);   // (16, 32)

    gemm_hmma<0><<<ggrid, 256, HG_SMEM>>>(Axp, Bqp, Qp, nullptr, nullptr);
    gemm_hmma<0><<<ggrid, 256, HG_SMEM>>>(Axp, Bkp, Kp, nullptr, nullptr);
    gemm_hmma<1><<<ggrid, 256, HG_SMEM>>>(Axp, Bvp, nullptr, Vhp, Vlp);

    rope_tables<<<(PS * 64 + 255) / 256, 256>>>(cp, sp);
    rope_split<<<PM, 256>>>(Qp, Kp, cp, sp, Q3p, K3p);

    attn_tc<<<dim3(PS / 128, PB * PH), 256, ATT_SMEM>>>(Q3p, K3p, Vhp, Vlp, Axp);

    gemm_hmma<0><<<ggrid, 256, HG_SMEM>>>(Axp, Bop, out, nullptr, nullptr);
}

// round 5
// speedup vs baseline: 3.2004x; 1.2122x over previous
#include <cuda_runtime.h>
#include <cuda_bf16.h>
#include <cuda_fp16.h>
#include <math.h>
#include <stdint.h>

// ---------------------------------------------------------------------------
// Problem constants
// ---------------------------------------------------------------------------
#define PB 2
#define PS 2048
#define PD 2048
#define PH 16
#define PHD 128
#define PM (PB * PS)          // 4096 rows
#define K3 (3 * PD)           // 6144: bf16 3-term split-K (Wo GEMM)
#define K2 (2 * PD)           // 4096: fp16 2-term split-K (QKV GEMMs)
#define ATT_SCALE 0.08838834764831845f

// ---------------------------------------------------------------------------
// Scratch (device globals; no allocation allowed)
// ---------------------------------------------------------------------------
__device__ float g_Q[(size_t)PM * PD];
__device__ float g_K[(size_t)PM * PD];
__device__ float g_cos[PS * (PHD / 2)];
__device__ float g_sin[PS * (PHD / 2)];
__device__ __half g_Ax2[(size_t)PM * K2];                // x, fp16 [hi|lo]
__device__ __half g_Bq2[(size_t)PD * K2];                // W, fp16 [hi|hi]
__device__ __half g_Bk2[(size_t)PD * K2];
__device__ __half g_Bv2[(size_t)PD * K2];
__device__ __nv_bfloat16 g_Ax3[(size_t)PM * K3];         // attn out, bf16 [hi|hi|lo]
__device__ __nv_bfloat16 g_Bo3[(size_t)PD * K3];         // Wo, bf16 [hi|lo|hi]
__device__ __nv_bfloat16 g_Q3[(size_t)PB * PH * PS * 384];   // [qh|qh|ql]*scale
__device__ __nv_bfloat16 g_K3[(size_t)PB * PH * PS * 384];   // [kh|kl|kh]
__device__ __nv_bfloat16 g_Vh[(size_t)PB * PH * PS * PHD];
__device__ __nv_bfloat16 g_Vl[(size_t)PB * PH * PS * PHD];

// ---------------------------------------------------------------------------
// PTX helpers (sm_80-compatible: cp.async + ldmatrix + mma.sync)
// ---------------------------------------------------------------------------
__device__ __forceinline__ uint32_t smem_u32(const void* p) {
    uint32_t a;
    asm("{ .reg .u64 t; cvta.to.shared.u64 t, %1; cvt.u32.u64 %0, t; }"
        : "=r"(a) : "l"(p));
    return a;
}

#define CP_ASYNC16(smem, gptr) \
    asm volatile("cp.async.cg.shared.global [%0], [%1], 16;" \
                 :: "r"(smem), "l"(gptr) : "memory")
#define CP_COMMIT() asm volatile("cp.async.commit_group;" ::: "memory")
#define CP_WAIT2()  asm volatile("cp.async.wait_group 2;" ::: "memory")
#define CP_WAIT0()  asm volatile("cp.async.wait_group 0;" ::: "memory")

#define LDSM_X4(r0, r1, r2, r3, addr) \
    asm volatile("ldmatrix.sync.aligned.m8n8.x4.shared.b16 {%0,%1,%2,%3}, [%4];" \
                 : "=r"(r0), "=r"(r1), "=r"(r2), "=r"(r3) : "r"(addr))
#define LDSM_X4T(r0, r1, r2, r3, addr) \
    asm volatile("ldmatrix.sync.aligned.m8n8.x4.trans.shared.b16 {%0,%1,%2,%3}, [%4];" \
                 : "=r"(r0), "=r"(r1), "=r"(r2), "=r"(r3) : "r"(addr))
#define LDSM_X2(r0, r1, addr) \
    asm volatile("ldmatrix.sync.aligned.m8n8.x2.shared.b16 {%0,%1}, [%2];" \
                 : "=r"(r0), "=r"(r1) : "r"(addr))

#define MMA_16816(c0, c1, c2, c3, a0, a1, a2, a3, b0, b1) \
    asm volatile("mma.sync.aligned.m16n8k16.row.col.f32.bf16.bf16.f32 " \
                 "{%0,%1,%2,%3}, {%4,%5,%6,%7}, {%8,%9}, {%0,%1,%2,%3};" \
                 : "+f"(c0), "+f"(c1), "+f"(c2), "+f"(c3) \
                 : "r"(a0), "r"(a1), "r"(a2), "r"(a3), "r"(b0), "r"(b1))

#define MMA_16816_F16(c0, c1, c2, c3, a0, a1, a2, a3, b0, b1) \
    asm volatile("mma.sync.aligned.m16n8k16.row.col.f32.f16.f16.f32 " \
                 "{%0,%1,%2,%3}, {%4,%5,%6,%7}, {%8,%9}, {%0,%1,%2,%3};" \
                 : "+f"(c0), "+f"(c1), "+f"(c2), "+f"(c3) \
                 : "r"(a0), "r"(a1), "r"(a2), "r"(a3), "r"(b0), "r"(b1))

// swizzles
__device__ __forceinline__ uint32_t swz64(int r, int ch) {   // 64B rows, 4x16B chunks
    return (uint32_t)(r * 64 + (((ch) ^ ((r >> 1) & 3)) << 4));
}
__device__ __forceinline__ uint32_t swzV(int r, int ch) {    // 256B rows, 16x16B chunks
    return (uint32_t)(r * 256 + (((ch) ^ (r & 7)) << 4));
}

// ---------------------------------------------------------------------------
// Split fp32 -> 3-segment bf16 (Wo path): order=0 (act): [hi|hi|lo]
//                                          order=1 (wgt): [hi|lo|hi]
// ---------------------------------------------------------------------------
__global__ void split3(const float* __restrict__ X, __nv_bfloat16* __restrict__ Y,
                       int order, int npairs)
{
    int i = blockIdx.x * blockDim.x + threadIdx.x;
    if (i >= npairs) return;
    int r = i >> 10;
    int c = (i & 1023) << 1;
    float2 v = *(const float2*)(X + (size_t)r * PD + c);
    __nv_bfloat16 h0 = __float2bfloat16(v.x);
    __nv_bfloat16 h1 = __float2bfloat16(v.y);
    __nv_bfloat16 l0 = __float2bfloat16(v.x - __bfloat162float(h0));
    __nv_bfloat16 l1 = __float2bfloat16(v.y - __bfloat162float(h1));
    __nv_bfloat162 hh = __halves2bfloat162(h0, h1);
    __nv_bfloat162 ll = __halves2bfloat162(l0, l1);
    __nv_bfloat162* base = (__nv_bfloat162*)(Y + (size_t)r * K3 + c);
    base[0]    = hh;
    base[1024] = order ? ll : hh;
    base[2048] = order ? hh : ll;
}

// ---------------------------------------------------------------------------
// Split fp32 -> 2-segment fp16 (QKV path): order=0 (act): [hi|lo]
//                                           order=1 (wgt): [hi|hi]
// ---------------------------------------------------------------------------
__global__ void split2(const float* __restrict__ X, __half* __restrict__ Y,
                       int order, int npairs)
{
    int i = blockIdx.x * blockDim.x + threadIdx.x;
    if (i >= npairs) return;
    int r = i >> 10;
    int c = (i & 1023) << 1;
    float2 v = *(const float2*)(X + (size_t)r * PD + c);
    __half h0 = __float2half(v.x);
    __half h1 = __float2half(v.y);
    __half2 hh = __halves2half2(h0, h1);
    __half2 seg1;
    if (order) {
        seg1 = hh;
    } else {
        __half l0 = __float2half(v.x - __half2float(h0));
        __half l1 = __float2half(v.y - __half2float(h1));
        seg1 = __halves2half2(l0, l1);
    }
    __half2* base = (__half2*)(Y + (size_t)r * K2 + c);
    base[0]    = hh;
    base[1024] = seg1;
}

// ---------------------------------------------------------------------------
// HMMA GEMM (round-3/4 body), templated on epilogue MODE, K-length, dtype.
//  MODE 0: fp32 C stores
//  MODE 1: V head-split -> Vh/Vl bf16 [b,h,s,128]
// ---------------------------------------------------------------------------
#define HG_BM 128
#define HG_BN 128
#define HG_BK 32
#define HG_STG 4
#define HG_STAGE_BYTES 16384
#define HG_SMEM (HG_STG * HG_STAGE_BYTES)

template<int MODE, int KTOT, bool FP16>
__global__ __launch_bounds__(256, 2)
void gemm_hmma(const uint16_t* __restrict__ A3,
               const uint16_t* __restrict__ B3,
               float* __restrict__ C,
               __nv_bfloat16* __restrict__ Vho,
               __nv_bfloat16* __restrict__ Vlo)
{
    constexpr int HG_KT = KTOT / HG_BK;
    extern __shared__ __align__(1024) char smem[];
    const uint32_t sbase = smem_u32(smem);

    const int tid  = threadIdx.x;
    const int lane = tid & 31;
    const int wid  = tid >> 5;
    const int wm   = wid & 1;
    const int wn   = wid >> 1;
    const int bm   = blockIdx.y * HG_BM;
    const int bn   = blockIdx.x * HG_BN;

    const uint16_t* Ag = A3 + (size_t)bm * KTOT;
    const uint16_t* Bg = B3 + (size_t)bn * KTOT;

    int lr[2], lc[2];
    uint32_t lsw[2];
    const uint16_t* gA[2];
    const uint16_t* gB[2];
#pragma unroll
    for (int p = 0; p < 2; ++p) {
        int idx = tid + p * 256;
        lr[p] = idx >> 2;
        lc[p] = idx & 3;
        lsw[p] = swz64(lr[p], lc[p]);
        gA[p] = Ag + (size_t)lr[p] * KTOT + lc[p] * 8;
        gB[p] = Bg + (size_t)lr[p] * KTOT + lc[p] * 8;
    }

    uint32_t a_row_off[4];
    int a_swz[4];
#pragma unroll
    for (int mi = 0; mi < 4; ++mi) {
        int r = wm * 64 + mi * 16 + (lane & 15);
        a_row_off[mi] = (uint32_t)(r * 64);
        a_swz[mi] = (r >> 1) & 3;
    }
    const int a_cpart = lane >> 4;
    uint32_t b_row_off[4];
    int b_swz[4];
#pragma unroll
    for (int nj = 0; nj < 4; ++nj) {
        int r = wn * 32 + nj * 8 + (lane & 7);
        b_row_off[nj] = (uint32_t)(r * 64);
        b_swz[nj] = (r >> 1) & 3;
    }
    const int b_cpart = (lane >> 3) & 1;

    float acc[4][4][4];
#pragma unroll
    for (int mi = 0; mi < 4; ++mi)
#pragma unroll
        for (int nj = 0; nj < 4; ++nj)
#pragma unroll
            for (int e = 0; e < 4; ++e) acc[mi][nj][e] = 0.0f;

#pragma unroll
    for (int s = 0; s < HG_STG - 1; ++s) {
        uint32_t sA = sbase + s * HG_STAGE_BYTES;
        uint32_t sB = sA + 8192;
        int k0 = s * HG_BK;
#pragma unroll
        for (int p = 0; p < 2; ++p) {
            CP_ASYNC16(sA + lsw[p], gA[p] + k0);
            CP_ASYNC16(sB + lsw[p], gB[p] + k0);
        }
        CP_COMMIT();
    }

    for (int kt = 0; kt < HG_KT; ++kt) {
        CP_WAIT2();
        __syncthreads();

        int nk = kt + HG_STG - 1;
        if (nk < HG_KT) {
            uint32_t sA = sbase + (nk & 3) * HG_STAGE_BYTES;
            uint32_t sB = sA + 8192;
            int k0 = nk * HG_BK;
#pragma unroll
            for (int p = 0; p < 2; ++p) {
                CP_ASYNC16(sA + lsw[p], gA[p] + k0);
                CP_ASYNC16(sB + lsw[p], gB[p] + k0);
            }
        }
        CP_COMMIT();

        uint32_t sA = sbase + (kt & 3) * HG_STAGE_BYTES;
        uint32_t sB = sA + 8192;
#pragma unroll
        for (int h = 0; h < 2; ++h) {
            uint32_t a0[4], a1[4], a2[4], a3[4];
#pragma unroll
            for (int mi = 0; mi < 4; ++mi) {
                uint32_t addr = sA + a_row_off[mi]
                              + (uint32_t)(((2 * h + a_cpart) ^ a_swz[mi]) << 4);
                LDSM_X4(a0[mi], a1[mi], a2[mi], a3[mi], addr);
            }
            uint32_t b0[4], b1[4];
#pragma unroll
            for (int nj = 0; nj < 4; ++nj) {
                uint32_t addr = sB + b_row_off[nj]
                              + (uint32_t)(((2 * h + b_cpart) ^ b_swz[nj]) << 4);
                LDSM_X2(b0[nj], b1[nj], addr);
            }
#pragma unroll
            for (int mi = 0; mi < 4; ++mi)
#pragma unroll
                for (int nj = 0; nj < 4; ++nj) {
                    if (FP16) {
                        MMA_16816_F16(acc[mi][nj][0], acc[mi][nj][1],
                                      acc[mi][nj][2], acc[mi][nj][3],
                                      a0[mi], a1[mi], a2[mi], a3[mi],
                                      b0[nj], b1[nj]);
                    } else {
                        MMA_16816(acc[mi][nj][0], acc[mi][nj][1],
                                  acc[mi][nj][2], acc[mi][nj][3],
                                  a0[mi], a1[mi], a2[mi], a3[mi],
                                  b0[nj], b1[nj]);
                    }
                }
        }
        __syncthreads();
    }

    const int erow = (lane >> 2);
    const int ecol = (lane & 3) * 2;
#pragma unroll
    for (int mi = 0; mi < 4; ++mi) {
#pragma unroll
        for (int nj = 0; nj < 4; ++nj) {
            int row = bm + wm * 64 + mi * 16 + erow;
            int col = bn + wn * 32 + nj * 8 + ecol;
            if (MODE == 0) {
                float2 v0 = make_float2(acc[mi][nj][0], acc[mi][nj][1]);
                float2 v1 = make_float2(acc[mi][nj][2], acc[mi][nj][3]);
                *(float2*)(C + (size_t)row * PD + col)       = v0;
                *(float2*)(C + (size_t)(row + 8) * PD + col) = v1;
            } else {
                int b = row >> 11, s = row & 2047;
                int h = col >> 7, hd = col & 127;
                size_t dst = ((size_t)(b * PH + h) * PS + s) * PHD + hd;
                float2 p0 = make_float2(acc[mi][nj][0], acc[mi][nj][1]);
                float2 p1 = make_float2(acc[mi][nj][2], acc[mi][nj][3]);
                __nv_bfloat162 h20 = __float22bfloat162_rn(p0);
                __nv_bfloat162 h21 = __float22bfloat162_rn(p1);
                float2 r0 = make_float2(p0.x - __bfloat162float(h20.x),
                                        p0.y - __bfloat162float(h20.y));
                float2 r1 = make_float2(p1.x - __bfloat162float(h21.x),
                                        p1.y - __bfloat162float(h21.y));
                *(__nv_bfloat162*)(Vho + dst)            = h20;
                *(__nv_bfloat162*)(Vho + dst + 8 * PHD)  = h21;
                *(__nv_bfloat162*)(Vlo + dst)            = __float22bfloat162_rn(r0);
                *(__nv_bfloat162*)(Vlo + dst + 8 * PHD)  = __float22bfloat162_rn(r1);
            }
        }
    }
}

// ---------------------------------------------------------------------------
// RoPE tables (fp64 trig on fp32-rounded angle chain)
// ---------------------------------------------------------------------------
__global__ void rope_tables(float* __restrict__ ct, float* __restrict__ st)
{
    int idx = blockIdx.x * blockDim.x + threadIdx.x;
    if (idx >= PS * (PHD / 2)) return;
    int s = idx >> 6;
    int j = idx & 63;
    float invf = (float)pow(10000.0, -(double)j / 64.0);
    float ang  = (float)s * invf;
    double a   = (double)ang;
    double cs, sn;
    sincos(a, &sn, &cs);
    ct[idx] = (float)cs;
    st[idx] = (float)sn;
}

// ---------------------------------------------------------------------------
// RoPE + scale + split: Q,K fp32 [b*s][2048] -> Q3 ([qh|qh|ql]*scale),
// K3 ([kh|kl|kh]); layout [b,h,s,384].
// ---------------------------------------------------------------------------
__global__ __launch_bounds__(256)
void rope_split(const float* __restrict__ Q, const float* __restrict__ Kf,
                const float* __restrict__ ct, const float* __restrict__ st,
                __nv_bfloat16* __restrict__ Q3, __nv_bfloat16* __restrict__ K3g)
{
    const int row = blockIdx.x;           // b*S + s
    const int b   = row >> 11;
    const int s   = row & (PS - 1);
    const int tid = threadIdx.x;
    __shared__ float buf[PD];

#pragma unroll
    for (int pass = 0; pass < 2; ++pass) {
        const float* src = (pass == 0 ? Q : Kf) + (size_t)row * PD;
        __nv_bfloat16* dstbase = pass == 0 ? Q3 : K3g;
        for (int i = tid; i < PD; i += 256) buf[i] = src[i];
        __syncthreads();
        for (int i = tid; i < PD; i += 256) {
            int d = i & (PHD - 1);
            int h = i >> 7;
            int j = d & 63;
            float c  = ct[s * 64 + j];
            float sn = st[s * 64 + j];
            float x  = buf[i];
            float xr = (d < 64) ? -buf[i + 64] : buf[i - 64];
            float val = fmaf(x, c, xr * sn);
            if (pass == 0) val *= ATT_SCALE;
            __nv_bfloat16 hi = __float2bfloat16(val);
            __nv_bfloat16 lo = __float2bfloat16(val - __bfloat162float(hi));
            __nv_bfloat16* out = dstbase
                + ((size_t)(b * PH + h) * PS + s) * 384 + d;
            if (pass == 0) { out[0] = hi; out[128] = hi; out[256] = lo; }
            else           { out[0] = hi; out[128] = lo; out[256] = hi; }
        }
        __syncthreads();
    }
}

// ---------------------------------------------------------------------------
// Tensor-core causal flash attention (proven round-4 body).
// CTA: 128 queries, 8 warps x 16 rows. Key tiles of 64.
// QK: K'=384 (3-term); PV: 3 passes (ph*vh, pl*vh, ph*vl).
// Output written directly as [hi|hi|lo] split into AX for the Wo GEMM.
// ---------------------------------------------------------------------------
#define ATS_Q  0
#define ATS_K  98304
#define ATS_VH 147456
#define ATS_VL 163840
#define ATS_P  180224
#define ATT_SMEM 212992

__global__ __launch_bounds__(256, 1)
void attn_tc(const __nv_bfloat16* __restrict__ Q3,
             const __nv_bfloat16* __restrict__ K3g,
             const __nv_bfloat16* __restrict__ Vh,
             const __nv_bfloat16* __restrict__ Vl,
             __nv_bfloat16* __restrict__ AX)
{
    extern __shared__ __align__(1024) char sm[];
    const uint32_t sb = smem_u32(sm);
    const int tid  = threadIdx.x;
    const int lane = tid & 31;
    const int w    = tid >> 5;
    const int qt   = 15 - (int)blockIdx.x;   // long tiles first
    const int bh   = blockIdx.y;
    const int qb   = qt * 128;
    const int nkt  = 2 * qt + 2;

    const __nv_bfloat16* q3 = Q3 + ((size_t)bh * PS + qb) * 384;
    const __nv_bfloat16* k3 = K3g + (size_t)bh * PS * 384;
    const __nv_bfloat16* vh = Vh + (size_t)bh * PS * PHD;
    const __nv_bfloat16* vl = Vl + (size_t)bh * PS * PHD;

#pragma unroll
    for (int p = 0; p < 12; ++p)
#pragma unroll
        for (int ps = 0; ps < 2; ++ps) {
            int idx = tid + ps * 256;
            int r = idx >> 2, ch = idx & 3;
            CP_ASYNC16(sb + ATS_Q + p * 8192 + swz64(r, ch),
                       q3 + (size_t)r * 384 + p * 32 + ch * 8);
        }
    {
        const __nv_bfloat16* kp = k3;
        int r = tid >> 2, ch = tid & 3;
#pragma unroll
        for (int p = 0; p < 12; ++p)
            CP_ASYNC16(sb + ATS_K + p * 4096 + swz64(r, ch),
                       kp + (size_t)r * 384 + p * 32 + ch * 8);
#pragma unroll
        for (int ps = 0; ps < 4; ++ps) {
            int idx = tid + ps * 256;
            int rr = idx >> 4, cc = idx & 15;
            CP_ASYNC16(sb + ATS_VH + swzV(rr, cc), vh + (size_t)rr * PHD + cc * 8);
            CP_ASYNC16(sb + ATS_VL + swzV(rr, cc), vl + (size_t)rr * PHD + cc * 8);
        }
    }
    CP_COMMIT();

    float m0 = -INFINITY, m1 = -INFINITY, l0 = 0.0f, l1 = 0.0f;
    float oa[16][4];
#pragma unroll
    for (int j = 0; j < 16; ++j)
#pragma unroll
        for (int e = 0; e < 4; ++e) oa[j][e] = 0.0f;

    const int arow  = w * 16 + (lane & 15);
    const int aswz  = (arow >> 1) & 3;
    const int acp   = lane >> 4;
    const int rr0   = w * 16 + (lane >> 2);
    const int prow0 = rr0;
    const int prow1 = rr0 + 8;
    const int pswz0 = (prow0 >> 1) & 3;
    const int pswz1 = (prow1 >> 1) & 3;
    const int vkrow_base = (lane & 7) + 8 * ((lane >> 3) & 1);

    for (int kt = 0; kt < nkt; ++kt) {
        CP_WAIT0();
        __syncthreads();

        float sa[8][4];
#pragma unroll
        for (int j = 0; j < 8; ++j)
#pragma unroll
            for (int e = 0; e < 4; ++e) sa[j][e] = 0.0f;

#pragma unroll
        for (int p = 0; p < 12; ++p) {
#pragma unroll
            for (int h = 0; h < 2; ++h) {
                uint32_t a0, a1, a2, a3;
                LDSM_X4(a0, a1, a2, a3,
                        sb + ATS_Q + p * 8192 + arow * 64
                           + (((2 * h + acp) ^ aswz) << 4));
#pragma unroll
                for (int jj = 0; jj < 4; ++jj) {
                    int brow = jj * 16 + (lane & 15);
                    uint32_t b0, b1, b2, b3;
                    LDSM_X4(b0, b1, b2, b3,
                            sb + ATS_K + p * 4096 + brow * 64
                               + (((2 * h + acp) ^ ((brow >> 1) & 3)) << 4));
                    MMA_16816(sa[2 * jj][0], sa[2 * jj][1], sa[2 * jj][2], sa[2 * jj][3],
                              a0, a1, a2, a3, b0, b2);
                    MMA_16816(sa[2 * jj + 1][0], sa[2 * jj + 1][1],
                              sa[2 * jj + 1][2], sa[2 * jj + 1][3],
                              a0, a1, a2, a3, b1, b3);
                }
            }
        }
        __syncthreads();

        if (kt + 1 < nkt) {
            const __nv_bfloat16* kp = k3 + (size_t)(kt + 1) * 64 * 384;
            int r = tid >> 2, ch = tid & 3;
#pragma unroll
            for (int p = 0; p < 12; ++p)
                CP_ASYNC16(sb + ATS_K + p * 4096 + swz64(r, ch),
                           kp + (size_t)r * 384 + p * 32 + ch * 8);
        }
        CP_COMMIT();

        const int kb = kt * 64;
        if (kt >= 2 * qt) {
            const int rg0 = qb + rr0;
            const int rg1 = rg0 + 8;
#pragma unroll
            for (int j = 0; j < 8; ++j) {
                int c0 = kb + j * 8 + 2 * (lane & 3);
                if (c0 > rg0)     sa[j][0] = -INFINITY;
                if (c0 + 1 > rg0) sa[j][1] = -INFINITY;
                if (c0 > rg1)     sa[j][2] = -INFINITY;
                if (c0 + 1 > rg1) sa[j][3] = -INFINITY;
            }
        }
        float rmax0 = -INFINITY, rmax1 = -INFINITY;
#pragma unroll
        for (int j = 0; j < 8; ++j) {
            rmax0 = fmaxf(rmax0, fmaxf(sa[j][0], sa[j][1]));
            rmax1 = fmaxf(rmax1, fmaxf(sa[j][2], sa[j][3]));
        }
        rmax0 = fmaxf(rmax0, __shfl_xor_sync(0xffffffffu, rmax0, 1));
        rmax0 = fmaxf(rmax0, __shfl_xor_sync(0xffffffffu, rmax0, 2));
        rmax1 = fmaxf(rmax1, __shfl_xor_sync(0xffffffffu, rmax1, 1));
        rmax1 = fmaxf(rmax1, __shfl_xor_sync(0xffffffffu, rmax1, 2));

        float mn0 = fmaxf(m0, rmax0);
        float mn1 = fmaxf(m1, rmax1);
        float corr0 = __expf(m0 - mn0);
        float corr1 = __expf(m1 - mn1);
        m0 = mn0; m1 = mn1;
#pragma unroll
        for (int j = 0; j < 16; ++j) {
            oa[j][0] *= corr0; oa[j][1] *= corr0;
            oa[j][2] *= corr1; oa[j][3] *= corr1;
        }
        float rs0 = 0.0f, rs1 = 0.0f;
#pragma unroll
        for (int j = 0; j < 8; ++j) {
            float p0 = __expf(sa[j][0] - mn0);
            float p1 = __expf(sa[j][1] - mn0);
            float p2 = __expf(sa[j][2] - mn1);
            float p3 = __expf(sa[j][3] - mn1);
            rs0 += p0 + p1;
            rs1 += p2 + p3;
            int key = j * 8 + 2 * (lane & 3);
            int panel = key >> 5, kin = key & 31;
            uint32_t inoff = (uint32_t)(((kin >> 3)) << 4) + ((kin & 7) << 1);
            __nv_bfloat162 h2a = __float22bfloat162_rn(make_float2(p0, p1));
            __nv_bfloat162 h2b = __float22bfloat162_rn(make_float2(p2, p3));
            __nv_bfloat162 l2a = __float22bfloat162_rn(make_float2(
                p0 - __bfloat162float(h2a.x), p1 - __bfloat162float(h2a.y)));
            __nv_bfloat162 l2b = __float22bfloat162_rn(make_float2(
                p2 - __bfloat162float(h2b.x), p3 - __bfloat162float(h2b.y)));
            uint32_t ba0 = (uint32_t)(ATS_P + panel * 8192) + prow0 * 64
                         + ((inoff & 0xF0u) ^ (pswz0 << 4)) + (inoff & 0xFu);
            uint32_t ba1 = (uint32_t)(ATS_P + panel * 8192) + prow1 * 64
                         + ((inoff & 0xF0u) ^ (pswz1 << 4)) + (inoff & 0xFu);
            *(__nv_bfloat162*)(sm + ba0)             = h2a;
            *(__nv_bfloat162*)(sm + ba1)             = h2b;
            *(__nv_bfloat162*)(sm + ba0 + 2 * 8192)  = l2a;
            *(__nv_bfloat162*)(sm + ba1 + 2 * 8192)  = l2b;
        }
        rs0 += __shfl_xor_sync(0xffffffffu, rs0, 1);
        rs0 += __shfl_xor_sync(0xffffffffu, rs0, 2);
        rs1 += __shfl_xor_sync(0xffffffffu, rs1, 1);
        rs1 += __shfl_xor_sync(0xffffffffu, rs1, 2);
        l0 = l0 * corr0 + rs0;
        l1 = l1 * corr1 + rs1;
        __syncwarp();

#pragma unroll
        for (int term = 0; term < 3; ++term) {
            const int ppan = (term == 1) ? 2 : 0;
            const uint32_t vbase = (term == 2) ? ATS_VL : ATS_VH;
#pragma unroll
            for (int s = 0; s < 4; ++s) {
                uint32_t a0, a1, a2, a3;
                LDSM_X4(a0, a1, a2, a3,
                        sb + ATS_P + (ppan + (s >> 1)) * 8192 + arow * 64
                           + (((2 * (s & 1) + acp) ^ aswz) << 4));
                int vk = s * 16 + vkrow_base;
#pragma unroll
                for (int g = 0; g < 8; ++g) {
                    uint32_t b0, b1, b2, b3;
                    LDSM_X4T(b0, b1, b2, b3,
                             sb + vbase + vk * 256
                                + ((((2 * g + (lane >> 4)) ^ (vk & 7))) << 4));
                    MMA_16816(oa[2 * g][0], oa[2 * g][1], oa[2 * g][2], oa[2 * g][3],
                              a0, a1, a2, a3, b0, b1);
                    MMA_16816(oa[2 * g + 1][0], oa[2 * g + 1][1],
                              oa[2 * g + 1][2], oa[2 * g + 1][3],
                              a0, a1, a2, a3, b2, b3);
                }
            }
        }
        __syncthreads();

        if (kt + 1 < nkt) {
            const __nv_bfloat16* va = vh + (size_t)(kt + 1) * 64 * PHD;
            const __nv_bfloat16* vb = vl + (size_t)(kt + 1) * 64 * PHD;
#pragma unroll
            for (int ps = 0; ps < 4; ++ps) {
                int idx = tid + ps * 256;
                int rr = idx >> 4, cc = idx & 15;
                CP_ASYNC16(sb + ATS_VH + swzV(rr, cc), va + (size_t)rr * PHD + cc * 8);
                CP_ASYNC16(sb + ATS_VL + swzV(rr, cc), vb + (size_t)rr * PHD + cc * 8);
            }
        }
        CP_COMMIT();
    }

    const float inv0 = 1.0f / l0;
    const float inv1 = 1.0f / l1;
    const int b = bh >> 4, h = bh & 15;
    const size_t row0 = (size_t)b * PS + qb + rr0;
    const size_t row1 = row0 + 8;
#pragma unroll
    for (int j = 0; j < 16; ++j) {
        int col = h * PHD + j * 8 + 2 * (lane & 3);
        float2 p0 = make_float2(oa[j][0] * inv0, oa[j][1] * inv0);
        float2 p1 = make_float2(oa[j][2] * inv1, oa[j][3] * inv1);
        __nv_bfloat162 h20 = __float22bfloat162_rn(p0);
        __nv_bfloat162 h21 = __float22bfloat162_rn(p1);
        __nv_bfloat162 l20 = __float22bfloat162_rn(make_float2(
            p0.x - __bfloat162float(h20.x), p0.y - __bfloat162float(h20.y)));
        __nv_bfloat162 l21 = __float22bfloat162_rn(make_float2(
            p1.x - __bfloat162float(h21.x), p1.y - __bfloat162float(h21.y)));
        __nv_bfloat16* d0 = AX + row0 * K3 + col;
        __nv_bfloat16* d1 = AX + row1 * K3 + col;
        *(__nv_bfloat162*)(d0)        = h20;
        *(__nv_bfloat162*)(d0 + 2048) = h20;
        *(__nv_bfloat162*)(d0 + 4096) = l20;
        *(__nv_bfloat162*)(d1)        = h21;
        *(__nv_bfloat162*)(d1 + 2048) = h21;
        *(__nv_bfloat162*)(d1 + 4096) = l21;
    }
}

// ---------------------------------------------------------------------------
// kernel_launch
// ---------------------------------------------------------------------------
extern "C" void kernel_launch(void* const* d_in, const int* in_sizes, int n_in,
                              void* d_out, int out_size)
{
    const float* x  = (const float*)d_in[0];
    const float* Wq = (const float*)d_in[1];
    const float* Wk = (const float*)d_in[2];
    const float* Wv = (const float*)d_in[3];
    const float* Wo = (const float*)d_in[4];
    float* out = (float*)d_out;

    float *Qp, *Kp, *cp, *sp;
    __half *Ax2p, *Bq2p, *Bk2p, *Bv2p;
    __nv_bfloat16 *Ax3p, *Bo3p, *Q3p, *K3p, *Vhp, *Vlp;
    cudaGetSymbolAddress((void**)&Qp,   g_Q);
    cudaGetSymbolAddress((void**)&Kp,   g_K);
    cudaGetSymbolAddress((void**)&cp,   g_cos);
    cudaGetSymbolAddress((void**)&sp,   g_sin);
    cudaGetSymbolAddress((void**)&Ax2p, g_Ax2);
    cudaGetSymbolAddress((void**)&Bq2p, g_Bq2);
    cudaGetSymbolAddress((void**)&Bk2p, g_Bk2);
    cudaGetSymbolAddress((void**)&Bv2p, g_Bv2);
    cudaGetSymbolAddress((void**)&Ax3p, g_Ax3);
    cudaGetSymbolAddress((void**)&Bo3p, g_Bo3);
    cudaGetSymbolAddress((void**)&Q3p,  g_Q3);
    cudaGetSymbolAddress((void**)&K3p,  g_K3);
    cudaGetSymbolAddress((void**)&Vhp,  g_Vh);
    cudaGetSymbolAddress((void**)&Vlp,  g_Vl);

    cudaFuncSetAttribute((const void*)gemm_hmma<0, K2, true>,
                         cudaFuncAttributeMaxDynamicSharedMemorySize, HG_SMEM);
    cudaFuncSetAttribute((const void*)gemm_hmma<1, K2, true>,
                         cudaFuncAttributeMaxDynamicSharedMemorySize, HG_SMEM);
    cudaFuncSetAttribute((const void*)gemm_hmma<0, K3, false>,
                         cudaFuncAttributeMaxDynamicSharedMemorySize, HG_SMEM);
    cudaFuncSetAttribute((const void*)attn_tc,
                         cudaFuncAttributeMaxDynamicSharedMemorySize, ATT_SMEM);

    const int wpairs = PD * PD / 2;
    const int xpairs = PM * PD / 2;

    // QKV path: fp16 2-term splits
    split2<<<(wpairs + 255) / 256, 256>>>(Wq, Bq2p, 1, wpairs);
    split2<<<(wpairs + 255) / 256, 256>>>(Wk, Bk2p, 1, wpairs);
    split2<<<(wpairs + 255) / 256, 256>>>(Wv, Bv2p, 1, wpairs);
    split2<<<(xpairs + 255) / 256, 256>>>(x,  Ax2p, 0, xpairs);
    // Wo path: bf16 3-term split
    split3<<<(wpairs + 255) / 256, 256>>>(Wo, Bo3p, 1, wpairs);

    dim3 ggrid(PD / HG_BN, PM / HG_BM);   // (16, 32)

    gemm_hmma<0, K2, true><<<ggrid, 256, HG_SMEM>>>(
        (const uint16_t*)Ax2p, (const uint16_t*)Bq2p, Qp, nullptr, nullptr);
    gemm_hmma<0, K2, true><<<ggrid, 256, HG_SMEM>>>(
        (const uint16_t*)Ax2p, (const uint16_t*)Bk2p, Kp, nullptr, nullptr);
    gemm_hmma<1, K2, true><<<ggrid, 256, HG_SMEM>>>(
        (const uint16_t*)Ax2p, (const uint16_t*)Bv2p, nullptr, Vhp, Vlp);

    rope_tables<<<(PS * 64 + 255) / 256, 256>>>(cp, sp);
    rope_split<<<PM, 256>>>(Qp, Kp, cp, sp, Q3p, K3p);

    attn_tc<<<dim3(PS / 128, PB * PH), 256, ATT_SMEM>>>(Q3p, K3p, Vhp, Vlp, Ax3p);

    gemm_hmma<0, K3, false><<<ggrid, 256, HG_SMEM>>>(
        (const uint16_t*)Ax3p, (const uint16_t*)Bo3p, out, nullptr, nullptr);
}

// round 6
// speedup vs baseline: 3.8104x; 1.1906x over previous
#include <cuda_runtime.h>
#include <cuda_fp16.h>
#include <math.h>
#include <stdint.h>

// ---------------------------------------------------------------------------
// Problem constants
// ---------------------------------------------------------------------------
#define PB 2
#define PS 2048
#define PD 2048
#define PH 16
#define PHD 128
#define PM (PB * PS)          // 4096 rows
#define K2 (2 * PD)           // 4096: fp16 2-term split-K
#define ATT_SCALE 0.08838834764831845f

// ---------------------------------------------------------------------------
// Scratch (device globals; no allocation allowed)
// ---------------------------------------------------------------------------
__device__ float g_Q[(size_t)PM * PD];
__device__ float g_K[(size_t)PM * PD];
__device__ float g_cos[PS * (PHD / 2)];
__device__ float g_sin[PS * (PHD / 2)];
__device__ __half g_Ax2[(size_t)PM * K2];                // x, fp16 [hi|lo]
__device__ __half g_Bq2[(size_t)PD * K2];                // W, fp16 [hi|hi]
__device__ __half g_Bk2[(size_t)PD * K2];
__device__ __half g_Bv2[(size_t)PD * K2];
__device__ __half g_Bo2[(size_t)PD * K2];
__device__ __half g_AxO[(size_t)PM * K2];                // attn out, fp16 [hi|lo]
__device__ __half g_Q2h[(size_t)PB * PH * PS * 256];     // [qh|ql]*scale
__device__ __half g_K2h[(size_t)PB * PH * PS * 256];     // [kh|kh]
__device__ __half g_Vh[(size_t)PB * PH * PS * PHD];

// ---------------------------------------------------------------------------
// PTX helpers (sm_80-compatible: cp.async + ldmatrix + mma.sync)
// ---------------------------------------------------------------------------
__device__ __forceinline__ uint32_t smem_u32(const void* p) {
    uint32_t a;
    asm("{ .reg .u64 t; cvta.to.shared.u64 t, %1; cvt.u32.u64 %0, t; }"
        : "=r"(a) : "l"(p));
    return a;
}

#define CP_ASYNC16(smem, gptr) \
    asm volatile("cp.async.cg.shared.global [%0], [%1], 16;" \
                 :: "r"(smem), "l"(gptr) : "memory")
#define CP_COMMIT() asm volatile("cp.async.commit_group;" ::: "memory")
#define CP_WAIT2()  asm volatile("cp.async.wait_group 2;" ::: "memory")
#define CP_WAIT0()  asm volatile("cp.async.wait_group 0;" ::: "memory")

#define LDSM_X4(r0, r1, r2, r3, addr) \
    asm volatile("ldmatrix.sync.aligned.m8n8.x4.shared.b16 {%0,%1,%2,%3}, [%4];" \
                 : "=r"(r0), "=r"(r1), "=r"(r2), "=r"(r3) : "r"(addr))
#define LDSM_X4T(r0, r1, r2, r3, addr) \
    asm volatile("ldmatrix.sync.aligned.m8n8.x4.trans.shared.b16 {%0,%1,%2,%3}, [%4];" \
                 : "=r"(r0), "=r"(r1), "=r"(r2), "=r"(r3) : "r"(addr))
#define LDSM_X2(r0, r1, addr) \
    asm volatile("ldmatrix.sync.aligned.m8n8.x2.shared.b16 {%0,%1}, [%2];" \
                 : "=r"(r0), "=r"(r1) : "r"(addr))

#define MMA_16816_F16(c0, c1, c2, c3, a0, a1, a2, a3, b0, b1) \
    asm volatile("mma.sync.aligned.m16n8k16.row.col.f32.f16.f16.f32 " \
                 "{%0,%1,%2,%3}, {%4,%5,%6,%7}, {%8,%9}, {%0,%1,%2,%3};" \
                 : "+f"(c0), "+f"(c1), "+f"(c2), "+f"(c3) \
                 : "r"(a0), "r"(a1), "r"(a2), "r"(a3), "r"(b0), "r"(b1))

// swizzles
__device__ __forceinline__ uint32_t swz64(int r, int ch) {   // 64B rows, 4x16B chunks
    return (uint32_t)(r * 64 + (((ch) ^ ((r >> 1) & 3)) << 4));
}
__device__ __forceinline__ uint32_t swzV(int r, int ch) {    // 256B rows, 16x16B chunks
    return (uint32_t)(r * 256 + (((ch) ^ (r & 7)) << 4));
}

// ---------------------------------------------------------------------------
// Split fp32 -> 2-segment fp16: order=0 (act): [hi|lo], order=1 (wgt): [hi|hi]
// ---------------------------------------------------------------------------
__global__ void split2(const float* __restrict__ X, __half* __restrict__ Y,
                       int order, int npairs)
{
    int i = blockIdx.x * blockDim.x + threadIdx.x;
    if (i >= npairs) return;
    int r = i >> 10;
    int c = (i & 1023) << 1;
    float2 v = *(const float2*)(X + (size_t)r * PD + c);
    __half h0 = __float2half(v.x);
    __half h1 = __float2half(v.y);
    __half2 hh = __halves2half2(h0, h1);
    __half2 seg1;
    if (order) {
        seg1 = hh;
    } else {
        __half l0 = __float2half(v.x - __half2float(h0));
        __half l1 = __float2half(v.y - __half2float(h1));
        seg1 = __halves2half2(l0, l1);
    }
    __half2* base = (__half2*)(Y + (size_t)r * K2 + c);
    base[0]    = hh;
    base[1024] = seg1;
}

// ---------------------------------------------------------------------------
// HMMA fp16 GEMM, K=4096, templated epilogue:
//  MODE 0: fp32 C stores
//  MODE 1: V head-gather -> Vh fp16 [b,h,s,128]
// ---------------------------------------------------------------------------
#define HG_BM 128
#define HG_BN 128
#define HG_BK 32
#define HG_STG 4
#define HG_STAGE_BYTES 16384
#define HG_SMEM (HG_STG * HG_STAGE_BYTES)
#define HG_KT (K2 / HG_BK)     // 128

template<int MODE>
__global__ __launch_bounds__(256, 2)
void gemm_hmma(const __half* __restrict__ A3,
               const __half* __restrict__ B3,
               float* __restrict__ C,
               __half* __restrict__ Vho)
{
    extern __shared__ __align__(1024) char smem[];
    const uint32_t sbase = smem_u32(smem);

    const int tid  = threadIdx.x;
    const int lane = tid & 31;
    const int wid  = tid >> 5;
    const int wm   = wid & 1;
    const int wn   = wid >> 1;
    const int bm   = blockIdx.y * HG_BM;
    const int bn   = blockIdx.x * HG_BN;

    const __half* Ag = A3 + (size_t)bm * K2;
    const __half* Bg = B3 + (size_t)bn * K2;

    int lr[2], lc[2];
    uint32_t lsw[2];
    const __half* gA[2];
    const __half* gB[2];
#pragma unroll
    for (int p = 0; p < 2; ++p) {
        int idx = tid + p * 256;
        lr[p] = idx >> 2;
        lc[p] = idx & 3;
        lsw[p] = swz64(lr[p], lc[p]);
        gA[p] = Ag + (size_t)lr[p] * K2 + lc[p] * 8;
        gB[p] = Bg + (size_t)lr[p] * K2 + lc[p] * 8;
    }

    uint32_t a_row_off[4];
    int a_swz[4];
#pragma unroll
    for (int mi = 0; mi < 4; ++mi) {
        int r = wm * 64 + mi * 16 + (lane & 15);
        a_row_off[mi] = (uint32_t)(r * 64);
        a_swz[mi] = (r >> 1) & 3;
    }
    const int a_cpart = lane >> 4;
    uint32_t b_row_off[4];
    int b_swz[4];
#pragma unroll
    for (int nj = 0; nj < 4; ++nj) {
        int r = wn * 32 + nj * 8 + (lane & 7);
        b_row_off[nj] = (uint32_t)(r * 64);
        b_swz[nj] = (r >> 1) & 3;
    }
    const int b_cpart = (lane >> 3) & 1;

    float acc[4][4][4];
#pragma unroll
    for (int mi = 0; mi < 4; ++mi)
#pragma unroll
        for (int nj = 0; nj < 4; ++nj)
#pragma unroll
            for (int e = 0; e < 4; ++e) acc[mi][nj][e] = 0.0f;

#pragma unroll
    for (int s = 0; s < HG_STG - 1; ++s) {
        uint32_t sA = sbase + s * HG_STAGE_BYTES;
        uint32_t sB = sA + 8192;
        int k0 = s * HG_BK;
#pragma unroll
        for (int p = 0; p < 2; ++p) {
            CP_ASYNC16(sA + lsw[p], gA[p] + k0);
            CP_ASYNC16(sB + lsw[p], gB[p] + k0);
        }
        CP_COMMIT();
    }

    for (int kt = 0; kt < HG_KT; ++kt) {
        CP_WAIT2();
        __syncthreads();

        int nk = kt + HG_STG - 1;
        if (nk < HG_KT) {
            uint32_t sA = sbase + (nk & 3) * HG_STAGE_BYTES;
            uint32_t sB = sA + 8192;
            int k0 = nk * HG_BK;
#pragma unroll
            for (int p = 0; p < 2; ++p) {
                CP_ASYNC16(sA + lsw[p], gA[p] + k0);
                CP_ASYNC16(sB + lsw[p], gB[p] + k0);
            }
        }
        CP_COMMIT();

        uint32_t sA = sbase + (kt & 3) * HG_STAGE_BYTES;
        uint32_t sB = sA + 8192;
#pragma unroll
        for (int h = 0; h < 2; ++h) {
            uint32_t a0[4], a1[4], a2[4], a3[4];
#pragma unroll
            for (int mi = 0; mi < 4; ++mi) {
                uint32_t addr = sA + a_row_off[mi]
                              + (uint32_t)(((2 * h + a_cpart) ^ a_swz[mi]) << 4);
                LDSM_X4(a0[mi], a1[mi], a2[mi], a3[mi], addr);
            }
            uint32_t b0[4], b1[4];
#pragma unroll
            for (int nj = 0; nj < 4; ++nj) {
                uint32_t addr = sB + b_row_off[nj]
                              + (uint32_t)(((2 * h + b_cpart) ^ b_swz[nj]) << 4);
                LDSM_X2(b0[nj], b1[nj], addr);
            }
#pragma unroll
            for (int mi = 0; mi < 4; ++mi)
#pragma unroll
                for (int nj = 0; nj < 4; ++nj)
                    MMA_16816_F16(acc[mi][nj][0], acc[mi][nj][1],
                                  acc[mi][nj][2], acc[mi][nj][3],
                                  a0[mi], a1[mi], a2[mi], a3[mi],
                                  b0[nj], b1[nj]);
        }
        __syncthreads();
    }

    const int erow = (lane >> 2);
    const int ecol = (lane & 3) * 2;
#pragma unroll
    for (int mi = 0; mi < 4; ++mi) {
#pragma unroll
        for (int nj = 0; nj < 4; ++nj) {
            int row = bm + wm * 64 + mi * 16 + erow;
            int col = bn + wn * 32 + nj * 8 + ecol;
            if (MODE == 0) {
                float2 v0 = make_float2(acc[mi][nj][0], acc[mi][nj][1]);
                float2 v1 = make_float2(acc[mi][nj][2], acc[mi][nj][3]);
                *(float2*)(C + (size_t)row * PD + col)       = v0;
                *(float2*)(C + (size_t)(row + 8) * PD + col) = v1;
            } else {
                int b = row >> 11, s = row & 2047;
                int h = col >> 7, hd = col & 127;
                size_t dst = ((size_t)(b * PH + h) * PS + s) * PHD + hd;
                __half2 h20 = __float22half2_rn(
                    make_float2(acc[mi][nj][0], acc[mi][nj][1]));
                __half2 h21 = __float22half2_rn(
                    make_float2(acc[mi][nj][2], acc[mi][nj][3]));
                *(__half2*)(Vho + dst)           = h20;
                *(__half2*)(Vho + dst + 8 * PHD) = h21;
            }
        }
    }
}

// ---------------------------------------------------------------------------
// RoPE tables (fp64 trig on fp32-rounded angle chain)
// ---------------------------------------------------------------------------
__global__ void rope_tables(float* __restrict__ ct, float* __restrict__ st)
{
    int idx = blockIdx.x * blockDim.x + threadIdx.x;
    if (idx >= PS * (PHD / 2)) return;
    int s = idx >> 6;
    int j = idx & 63;
    float invf = (float)pow(10000.0, -(double)j / 64.0);
    float ang  = (float)s * invf;
    double a   = (double)ang;
    double cs, sn;
    sincos(a, &sn, &cs);
    ct[idx] = (float)cs;
    st[idx] = (float)sn;
}

// ---------------------------------------------------------------------------
// RoPE + scale + fp16 split: Q -> [qh|ql]*scale, K -> [kh|kh]; [b,h,s,256].
// ---------------------------------------------------------------------------
__global__ __launch_bounds__(256)
void rope_split(const float* __restrict__ Q, const float* __restrict__ Kf,
                const float* __restrict__ ct, const float* __restrict__ st,
                __half* __restrict__ Q2, __half* __restrict__ K2g)
{
    const int row = blockIdx.x;           // b*S + s
    const int b   = row >> 11;
    const int s   = row & (PS - 1);
    const int tid = threadIdx.x;
    __shared__ float buf[PD];

#pragma unroll
    for (int pass = 0; pass < 2; ++pass) {
        const float* src = (pass == 0 ? Q : Kf) + (size_t)row * PD;
        __half* dstbase = pass == 0 ? Q2 : K2g;
        for (int i = tid; i < PD; i += 256) buf[i] = src[i];
        __syncthreads();
        for (int i = tid; i < PD; i += 256) {
            int d = i & (PHD - 1);
            int h = i >> 7;
            int j = d & 63;
            float c  = ct[s * 64 + j];
            float sn = st[s * 64 + j];
            float x  = buf[i];
            float xr = (d < 64) ? -buf[i + 64] : buf[i - 64];
            float val = fmaf(x, c, xr * sn);
            if (pass == 0) val *= ATT_SCALE;
            __half hi = __float2half(val);
            __half* out = dstbase + ((size_t)(b * PH + h) * PS + s) * 256 + d;
            out[0] = hi;
            out[128] = (pass == 0) ? __float2half(val - __half2float(hi)) : hi;
        }
        __syncthreads();
    }
}

// ---------------------------------------------------------------------------
// Tensor-core causal flash attention, fp16 2-term throughout.
// CTA: 128 queries, 8 warps x 16 rows. Key tiles of 64.
// QK: K'=256 ([qh|ql]x[kh|kh]); PV: 2 passes ((ph+pl)*vh).
// Output written directly as [hi|lo] fp16 split for the Wo GEMM.
// ---------------------------------------------------------------------------
#define ATS_Q  0          // 8 panels x 8192 = 65536
#define ATS_K  65536      // 8 panels x 4096 = 32768
#define ATS_VH 98304      // 16384
#define ATS_P  114688     // 4 panels x 8192 = 32768
#define ATT_SMEM 147456

__global__ __launch_bounds__(256, 1)
void attn_tc(const __half* __restrict__ Q2,
             const __half* __restrict__ K2g,
             const __half* __restrict__ Vh,
             __half* __restrict__ AXO)
{
    extern __shared__ __align__(1024) char sm[];
    const uint32_t sb = smem_u32(sm);
    const int tid  = threadIdx.x;
    const int lane = tid & 31;
    const int w    = tid >> 5;
    const int qt   = 15 - (int)blockIdx.x;   // long tiles first
    const int bh   = blockIdx.y;
    const int qb   = qt * 128;
    const int nkt  = 2 * qt + 2;

    const __half* q2 = Q2 + ((size_t)bh * PS + qb) * 256;
    const __half* k2 = K2g + (size_t)bh * PS * 256;
    const __half* vh = Vh + (size_t)bh * PS * PHD;

    // Q tile (128 x 256)
#pragma unroll
    for (int p = 0; p < 8; ++p)
#pragma unroll
        for (int ps = 0; ps < 2; ++ps) {
            int idx = tid + ps * 256;
            int r = idx >> 2, ch = idx & 3;
            CP_ASYNC16(sb + ATS_Q + p * 8192 + swz64(r, ch),
                       q2 + (size_t)r * 256 + p * 32 + ch * 8);
        }
    // K0, V0
    {
        int r = tid >> 2, ch = tid & 3;
#pragma unroll
        for (int p = 0; p < 8; ++p)
            CP_ASYNC16(sb + ATS_K + p * 4096 + swz64(r, ch),
                       k2 + (size_t)r * 256 + p * 32 + ch * 8);
#pragma unroll
        for (int ps = 0; ps < 4; ++ps) {
            int idx = tid + ps * 256;
            int rr = idx >> 4, cc = idx & 15;
            CP_ASYNC16(sb + ATS_VH + swzV(rr, cc), vh + (size_t)rr * PHD + cc * 8);
        }
    }
    CP_COMMIT();

    float m0 = -INFINITY, m1 = -INFINITY, l0 = 0.0f, l1 = 0.0f;
    float oa[16][4];
#pragma unroll
    for (int j = 0; j < 16; ++j)
#pragma unroll
        for (int e = 0; e < 4; ++e) oa[j][e] = 0.0f;

    const int arow  = w * 16 + (lane & 15);
    const int aswz  = (arow >> 1) & 3;
    const int acp   = lane >> 4;
    const int rr0   = w * 16 + (lane >> 2);
    const int prow0 = rr0;
    const int prow1 = rr0 + 8;
    const int pswz0 = (prow0 >> 1) & 3;
    const int pswz1 = (prow1 >> 1) & 3;
    const int vkrow_base = (lane & 7) + 8 * ((lane >> 3) & 1);

    for (int kt = 0; kt < nkt; ++kt) {
        CP_WAIT0();
        __syncthreads();

        // ============ QK: S[16 x 64] per warp, K'=256 ============
        float sa[8][4];
#pragma unroll
        for (int j = 0; j < 8; ++j)
#pragma unroll
            for (int e = 0; e < 4; ++e) sa[j][e] = 0.0f;

#pragma unroll
        for (int p = 0; p < 8; ++p) {
#pragma unroll
            for (int h = 0; h < 2; ++h) {
                uint32_t a0, a1, a2, a3;
                LDSM_X4(a0, a1, a2, a3,
                        sb + ATS_Q + p * 8192 + arow * 64
                           + (((2 * h + acp) ^ aswz) << 4));
#pragma unroll
                for (int jj = 0; jj < 4; ++jj) {
                    int brow = jj * 16 + (lane & 15);
                    uint32_t b0, b1, b2, b3;
                    LDSM_X4(b0, b1, b2, b3,
                            sb + ATS_K + p * 4096 + brow * 64
                               + (((2 * h + acp) ^ ((brow >> 1) & 3)) << 4));
                    MMA_16816_F16(sa[2 * jj][0], sa[2 * jj][1],
                                  sa[2 * jj][2], sa[2 * jj][3],
                                  a0, a1, a2, a3, b0, b2);
                    MMA_16816_F16(sa[2 * jj + 1][0], sa[2 * jj + 1][1],
                                  sa[2 * jj + 1][2], sa[2 * jj + 1][3],
                                  a0, a1, a2, a3, b1, b3);
                }
            }
        }
        __syncthreads();

        // prefetch next K under softmax+PV
        if (kt + 1 < nkt) {
            const __half* kp = k2 + (size_t)(kt + 1) * 64 * 256;
            int r = tid >> 2, ch = tid & 3;
#pragma unroll
            for (int p = 0; p < 8; ++p)
                CP_ASYNC16(sb + ATS_K + p * 4096 + swz64(r, ch),
                           kp + (size_t)r * 256 + p * 32 + ch * 8);
        }
        CP_COMMIT();

        // ============ online softmax ============
        const int kb = kt * 64;
        if (kt >= 2 * qt) {
            const int rg0 = qb + rr0;
            const int rg1 = rg0 + 8;
#pragma unroll
            for (int j = 0; j < 8; ++j) {
                int c0 = kb + j * 8 + 2 * (lane & 3);
                if (c0 > rg0)     sa[j][0] = -INFINITY;
                if (c0 + 1 > rg0) sa[j][1] = -INFINITY;
                if (c0 > rg1)     sa[j][2] = -INFINITY;
                if (c0 + 1 > rg1) sa[j][3] = -INFINITY;
            }
        }
        float rmax0 = -INFINITY, rmax1 = -INFINITY;
#pragma unroll
        for (int j = 0; j < 8; ++j) {
            rmax0 = fmaxf(rmax0, fmaxf(sa[j][0], sa[j][1]));
            rmax1 = fmaxf(rmax1, fmaxf(sa[j][2], sa[j][3]));
        }
        rmax0 = fmaxf(rmax0, __shfl_xor_sync(0xffffffffu, rmax0, 1));
        rmax0 = fmaxf(rmax0, __shfl_xor_sync(0xffffffffu, rmax0, 2));
        rmax1 = fmaxf(rmax1, __shfl_xor_sync(0xffffffffu, rmax1, 1));
        rmax1 = fmaxf(rmax1, __shfl_xor_sync(0xffffffffu, rmax1, 2));

        float mn0 = fmaxf(m0, rmax0);
        float mn1 = fmaxf(m1, rmax1);
        float corr0 = __expf(m0 - mn0);
        float corr1 = __expf(m1 - mn1);
        m0 = mn0; m1 = mn1;
#pragma unroll
        for (int j = 0; j < 16; ++j) {
            oa[j][0] *= corr0; oa[j][1] *= corr0;
            oa[j][2] *= corr1; oa[j][3] *= corr1;
        }
        float rs0 = 0.0f, rs1 = 0.0f;
#pragma unroll
        for (int j = 0; j < 8; ++j) {
            float p0 = __expf(sa[j][0] - mn0);
            float p1 = __expf(sa[j][1] - mn0);
            float p2 = __expf(sa[j][2] - mn1);
            float p3 = __expf(sa[j][3] - mn1);
            rs0 += p0 + p1;
            rs1 += p2 + p3;
            // write [ph panels 0,1 | pl panels 2,3]
            int key = j * 8 + 2 * (lane & 3);
            int panel = key >> 5, kin = key & 31;
            uint32_t inoff = (uint32_t)(((kin >> 3)) << 4) + ((kin & 7) << 1);
            __half2 h2a = __float22half2_rn(make_float2(p0, p1));
            __half2 h2b = __float22half2_rn(make_float2(p2, p3));
            __half2 l2a = __float22half2_rn(make_float2(
                p0 - __half2float(__low2half(h2a)),
                p1 - __half2float(__high2half(h2a))));
            __half2 l2b = __float22half2_rn(make_float2(
                p2 - __half2float(__low2half(h2b)),
                p3 - __half2float(__high2half(h2b))));
            uint32_t ba0 = (uint32_t)(ATS_P + panel * 8192) + prow0 * 64
                         + ((inoff & 0xF0u) ^ (pswz0 << 4)) + (inoff & 0xFu);
            uint32_t ba1 = (uint32_t)(ATS_P + panel * 8192) + prow1 * 64
                         + ((inoff & 0xF0u) ^ (pswz1 << 4)) + (inoff & 0xFu);
            *(__half2*)(sm + ba0)            = h2a;
            *(__half2*)(sm + ba1)            = h2b;
            *(__half2*)(sm + ba0 + 2 * 8192) = l2a;
            *(__half2*)(sm + ba1 + 2 * 8192) = l2b;
        }
        rs0 += __shfl_xor_sync(0xffffffffu, rs0, 1);
        rs0 += __shfl_xor_sync(0xffffffffu, rs0, 2);
        rs1 += __shfl_xor_sync(0xffffffffu, rs1, 1);
        rs1 += __shfl_xor_sync(0xffffffffu, rs1, 2);
        l0 = l0 * corr0 + rs0;
        l1 = l1 * corr1 + rs1;
        __syncwarp();

        // ============ PV: O += (ph + pl) x vh ============
#pragma unroll
        for (int term = 0; term < 2; ++term) {
            const int ppan = 2 * term;
#pragma unroll
            for (int s = 0; s < 4; ++s) {
                uint32_t a0, a1, a2, a3;
                LDSM_X4(a0, a1, a2, a3,
                        sb + ATS_P + (ppan + (s >> 1)) * 8192 + arow * 64
                           + (((2 * (s & 1) + acp) ^ aswz) << 4));
                int vk = s * 16 + vkrow_base;
#pragma unroll
                for (int g = 0; g < 8; ++g) {
                    uint32_t b0, b1, b2, b3;
                    LDSM_X4T(b0, b1, b2, b3,
                             sb + ATS_VH + vk * 256
                                + ((((2 * g + (lane >> 4)) ^ (vk & 7))) << 4));
                    MMA_16816_F16(oa[2 * g][0], oa[2 * g][1],
                                  oa[2 * g][2], oa[2 * g][3],
                                  a0, a1, a2, a3, b0, b1);
                    MMA_16816_F16(oa[2 * g + 1][0], oa[2 * g + 1][1],
                                  oa[2 * g + 1][2], oa[2 * g + 1][3],
                                  a0, a1, a2, a3, b2, b3);
                }
            }
        }
        __syncthreads();

        // prefetch next V
        if (kt + 1 < nkt) {
            const __half* va = vh + (size_t)(kt + 1) * 64 * PHD;
#pragma unroll
            for (int ps = 0; ps < 4; ++ps) {
                int idx = tid + ps * 256;
                int rr = idx >> 4, cc = idx & 15;
                CP_ASYNC16(sb + ATS_VH + swzV(rr, cc), va + (size_t)rr * PHD + cc * 8);
            }
        }
        CP_COMMIT();
    }

    // ============ epilogue: [hi|lo] fp16 split for the Wo GEMM ============
    const float inv0 = 1.0f / l0;
    const float inv1 = 1.0f / l1;
    const int b = bh >> 4, h = bh & 15;
    const size_t row0 = (size_t)b * PS + qb + rr0;
    const size_t row1 = row0 + 8;
#pragma unroll
    for (int j = 0; j < 16; ++j) {
        int col = h * PHD + j * 8 + 2 * (lane & 3);
        float2 p0 = make_float2(oa[j][0] * inv0, oa[j][1] * inv0);
        float2 p1 = make_float2(oa[j][2] * inv1, oa[j][3] * inv1);
        __half2 h20 = __float22half2_rn(p0);
        __half2 h21 = __float22half2_rn(p1);
        __half2 l20 = __float22half2_rn(make_float2(
            p0.x - __half2float(__low2half(h20)),
            p0.y - __half2float(__high2half(h20))));
        __half2 l21 = __float22half2_rn(make_float2(
            p1.x - __half2float(__low2half(h21)),
            p1.y - __half2float(__high2half(h21))));
        __half* d0 = AXO + row0 * K2 + col;
        __half* d1 = AXO + row1 * K2 + col;
        *(__half2*)(d0)        = h20;
        *(__half2*)(d0 + 2048) = l20;
        *(__half2*)(d1)        = h21;
        *(__half2*)(d1 + 2048) = l21;
    }
}

// ---------------------------------------------------------------------------
// kernel_launch
// ---------------------------------------------------------------------------
extern "C" void kernel_launch(void* const* d_in, const int* in_sizes, int n_in,
                              void* d_out, int out_size)
{
    const float* x  = (const float*)d_in[0];
    const float* Wq = (const float*)d_in[1];
    const float* Wk = (const float*)d_in[2];
    const float* Wv = (const float*)d_in[3];
    const float* Wo = (const float*)d_in[4];
    float* out = (float*)d_out;

    float *Qp, *Kp, *cp, *sp;
    __half *Ax2p, *Bq2p, *Bk2p, *Bv2p, *Bo2p, *AxOp, *Q2p, *K2p, *Vhp;
    cudaGetSymbolAddress((void**)&Qp,   g_Q);
    cudaGetSymbolAddress((void**)&Kp,   g_K);
    cudaGetSymbolAddress((void**)&cp,   g_cos);
    cudaGetSymbolAddress((void**)&sp,   g_sin);
    cudaGetSymbolAddress((void**)&Ax2p, g_Ax2);
    cudaGetSymbolAddress((void**)&Bq2p, g_Bq2);
    cudaGetSymbolAddress((void**)&Bk2p, g_Bk2);
    cudaGetSymbolAddress((void**)&Bv2p, g_Bv2);
    cudaGetSymbolAddress((void**)&Bo2p, g_Bo2);
    cudaGetSymbolAddress((void**)&AxOp, g_AxO);
    cudaGetSymbolAddress((void**)&Q2p,  g_Q2h);
    cudaGetSymbolAddress((void**)&K2p,  g_K2h);
    cudaGetSymbolAddress((void**)&Vhp,  g_Vh);

    cudaFuncSetAttribute((const void*)gemm_hmma<0>,
                         cudaFuncAttributeMaxDynamicSharedMemorySize, HG_SMEM);
    cudaFuncSetAttribute((const void*)gemm_hmma<1>,
                         cudaFuncAttributeMaxDynamicSharedMemorySize, HG_SMEM);
    cudaFuncSetAttribute((const void*)attn_tc,
                         cudaFuncAttributeMaxDynamicSharedMemorySize, ATT_SMEM);

    const int wpairs = PD * PD / 2;
    const int xpairs = PM * PD / 2;

    split2<<<(wpairs + 255) / 256, 256>>>(Wq, Bq2p, 1, wpairs);
    split2<<<(wpairs + 255) / 256, 256>>>(Wk, Bk2p, 1, wpairs);
    split2<<<(wpairs + 255) / 256, 256>>>(Wv, Bv2p, 1, wpairs);
    split2<<<(wpairs + 255) / 256, 256>>>(Wo, Bo2p, 1, wpairs);
    split2<<<(xpairs + 255) / 256, 256>>>(x,  Ax2p, 0, xpairs);

    dim3 ggrid(PD / HG_BN, PM / HG_BM);   // (16, 32)

    gemm_hmma<0><<<ggrid, 256, HG_SMEM>>>(Ax2p, Bq2p, Qp, nullptr);
    gemm_hmma<0><<<ggrid, 256, HG_SMEM>>>(Ax2p, Bk2p, Kp, nullptr);
    gemm_hmma<1><<<ggrid, 256, HG_SMEM>>>(Ax2p, Bv2p, nullptr, Vhp);

    rope_tables<<<(PS * 64 + 255) / 256, 256>>>(cp, sp);
    rope_split<<<PM, 256>>>(Qp, Kp, cp, sp, Q2p, K2p);

    attn_tc<<<dim3(PS / 128, PB * PH), 256, ATT_SMEM>>>(Q2p, K2p, Vhp, AxOp);

    gemm_hmma<0><<<ggrid, 256, HG_SMEM>>>(AxOp, Bo2p, out, nullptr);
}